// round 11
// baseline (speedup 1.0000x reference)
#include <cuda_runtime.h>
#include <cuda_fp16.h>
#include <stdint.h>
#include <math.h>

#define NB 2
#define NS 2048
#define ND 2048
#define NH 16
#define NDH 128
#define NM (NB*NS)

// Scratch (device globals; no allocation allowed)
__device__ __half g_qh[(size_t)NB*NH*NS*NDH];
__device__ __half g_kh[(size_t)NB*NH*NS*NDH];
__device__ __half g_vt[(size_t)NB*NH*NDH*NS];   // V transposed: [b,h,dh,s] fp16
__device__ __half g_ctx[(size_t)NB*NS*ND];      // attention output, fp16
__device__ __half g_xh[(size_t)NM*ND];          // x in fp16
__device__ __half g_wqh[(size_t)ND*ND];
__device__ __half g_wkh[(size_t)ND*ND];
__device__ __half g_wvh[(size_t)ND*ND];
__device__ __half g_woh[(size_t)ND*ND];

__device__ __forceinline__ unsigned packh2(float lo, float hi) {
  __half2 h = __floats2half2_rn(lo, hi);
  return *(unsigned*)&h;
}
__device__ __forceinline__ void mma_f16(float* c, unsigned a0, unsigned a1,
                                        unsigned a2, unsigned a3,
                                        unsigned b0, unsigned b1) {
  asm volatile(
    "mma.sync.aligned.m16n8k16.row.col.f32.f16.f16.f32 "
    "{%0,%1,%2,%3},{%4,%5,%6,%7},{%8,%9},{%0,%1,%2,%3};\n"
    : "+f"(c[0]), "+f"(c[1]), "+f"(c[2]), "+f"(c[3])
    : "r"(a0), "r"(a1), "r"(a2), "r"(a3), "r"(b0), "r"(b1));
}
__device__ __forceinline__ void ldsm4(unsigned& r0, unsigned& r1,
                                      unsigned& r2, unsigned& r3,
                                      uint32_t addr) {
  asm volatile(
    "ldmatrix.sync.aligned.m8n8.x4.shared.b16 {%0,%1,%2,%3}, [%4];"
    : "=r"(r0), "=r"(r1), "=r"(r2), "=r"(r3) : "r"(addr));
}
__device__ __forceinline__ void cpasync16(uint32_t dst, const void* src) {
  asm volatile("cp.async.cg.shared.global [%0], [%1], 16;" :: "r"(dst),
               "l"(src));
}

// fp32 -> fp16 conversion, vectorized.
__global__ void tohalf_k(const float* __restrict__ src,
                         __half* __restrict__ dst, int n4) {
  int i = blockIdx.x * 256 + threadIdx.x;
  if (i < n4) {
    float4 v = ((const float4*)src)[i];
    __half2 h0 = __floats2half2_rn(v.x, v.y);
    __half2 h1 = __floats2half2_rn(v.z, v.w);
    uint2 u = {*(unsigned*)&h0, *(unsigned*)&h1};
    ((uint2*)dst)[i] = u;
  }
}

// 4 weight matrices (ND*ND each) in one launch.
__global__ void tohalf4_k(const float* __restrict__ s0, const float* __restrict__ s1,
                          const float* __restrict__ s2, const float* __restrict__ s3,
                          __half* __restrict__ d0, __half* __restrict__ d1,
                          __half* __restrict__ d2, __half* __restrict__ d3) {
  const int per = (ND * ND / 4) / 256;       // blocks per tensor
  const int which = blockIdx.x / per;
  const int i = (blockIdx.x % per) * 256 + threadIdx.x;
  const float* src = (which == 0) ? s0 : (which == 1) ? s1 : (which == 2) ? s2 : s3;
  __half* dst = (which == 0) ? d0 : (which == 1) ? d1 : (which == 2) ? d2 : d3;
  float4 v = ((const float4*)src)[i];
  __half2 h0 = __floats2half2_rn(v.x, v.y);
  __half2 h1 = __floats2half2_rn(v.z, v.w);
  uint2 u = {*(unsigned*)&h0, *(unsigned*)&h1};
  ((uint2*)dst)[i] = u;
}

// ============================================================================
// GEMM: fp16 mma.sync + ldmatrix, cp.async 3-stage.
// Block tile 256x128, 8 warps (4x2), warp tile 64x64 (64 HMMA per K-tile
// per warp). 1 CTA/SM. Smem rows: 32 halves = 16 words, pitch 20.
// ============================================================================
#define GA_STAGEW 5120                 // A: 256 rows * 20 words
#define GB_STAGEW 2560                 // B: 128 rows * 20 words
#define GH_SMEM (3 * (GA_STAGEW + GB_STAGEW) * 4)

template<int MODE>
__global__ void __launch_bounds__(256, 1) gemm_h(
    const __half* __restrict__ A, const __half* __restrict__ W,
    float* __restrict__ C, __half* __restrict__ Ch,
    const float* __restrict__ fcos, const float* __restrict__ fsin,
    float outscale)
{
  extern __shared__ unsigned smh[];
  unsigned* As = smh;                    // [3][256][20]
  unsigned* Bs = smh + 3 * GA_STAGEW;    // [3][128][20]
  const int K = ND;
  const int bm = blockIdx.y * 256;
  const int bn = blockIdx.x * 128;
  const int tid = threadIdx.x;
  const int warp = tid >> 5, lane = tid & 31;
  const int wm0 = (warp >> 1) * 64;
  const int wn0 = (warp & 1) * 64;
  const int g = lane >> 2, tk = lane & 3;
  const int l8 = lane & 7, lm = lane >> 3;   // ldmatrix: row-in-8x8, matrix id

  const uint32_t sa = (uint32_t)__cvta_generic_to_shared(As);
  const uint32_t sbm = (uint32_t)__cvta_generic_to_shared(Bs);

  // Per-thread ldmatrix byte offsets within a stage (add ks*32 for k-halves).
  // A (a0..a3 = [m0-7,k0-7],[m8-15,k0-7],[m0-7,k8-15],[m8-15,k8-15]):
  uint32_t aoff[4];
  #pragma unroll
  for (int mi = 0; mi < 4; mi++)
    aoff[mi] = (uint32_t)(((wm0 + mi * 16 + l8 + (lm & 1) * 8) * 20
                           + (lm >> 1) * 4) * 4);
  // B (mat0..3 = [n0-7,k0-7],[n0-7,k8-15],[n8-15,k0-7],[n8-15,k8-15]):
  uint32_t boff[4];
  #pragma unroll
  for (int n2 = 0; n2 < 4; n2++)
    boff[n2] = (uint32_t)(((wn0 + n2 * 16 + l8 + (lm >> 1) * 8) * 20
                           + (lm & 1) * 4) * 4);

  float acc[4][8][4];
  #pragma unroll
  for (int mi = 0; mi < 4; mi++)
    #pragma unroll
    for (int ni = 0; ni < 8; ni++)
      #pragma unroll
      for (int cc = 0; cc < 4; cc++) acc[mi][ni][cc] = 0.f;

  // A: 1024 16B-chunks (4/thread), B: 512 (2/thread)
  #define GH_ISSUE(kt, st) do { \
    _Pragma("unroll") \
    for (int i = 0; i < 4; i++) { \
      const int id = tid + 256 * i; \
      const int r = id >> 2, c = id & 3; \
      const uint32_t wo = (uint32_t)((st) * GA_STAGEW + r * 20 + c * 4) * 4; \
      cpasync16(sa + wo, A + (size_t)(bm + r) * K + (kt) * 32 + c * 8); \
    } \
    _Pragma("unroll") \
    for (int i = 0; i < 2; i++) { \
      const int id = tid + 256 * i; \
      const int r = id >> 2, c = id & 3; \
      const uint32_t wo = (uint32_t)((st) * GB_STAGEW + r * 20 + c * 4) * 4; \
      cpasync16(sbm + wo, W + (size_t)(bn + r) * K + (kt) * 32 + c * 8); \
    } \
    asm volatile("cp.async.commit_group;" ::); \
  } while (0)

  GH_ISSUE(0, 0);
  GH_ISSUE(1, 1);

  const int niter = K / 32;   // 64
  int st_c = 0, st_p = 2;
  for (int kt = 0; kt < niter; kt++) {
    asm volatile("cp.async.wait_group 1;" ::);
    __syncthreads();
    if (kt + 2 < niter) GH_ISSUE(kt + 2, st_p);
    else asm volatile("cp.async.commit_group;" ::);

    const uint32_t ab = sa + (uint32_t)st_c * GA_STAGEW * 4;
    const uint32_t bb = sbm + (uint32_t)st_c * GB_STAGEW * 4;
    #pragma unroll
    for (int ks = 0; ks < 2; ks++) {
      unsigned afr[4][4], bfr[8][2];
      #pragma unroll
      for (int mi = 0; mi < 4; mi++)
        ldsm4(afr[mi][0], afr[mi][1], afr[mi][2], afr[mi][3],
              ab + aoff[mi] + ks * 32);
      #pragma unroll
      for (int n2 = 0; n2 < 4; n2++)
        ldsm4(bfr[2 * n2][0], bfr[2 * n2][1], bfr[2 * n2 + 1][0],
              bfr[2 * n2 + 1][1], bb + boff[n2] + ks * 32);
      #pragma unroll
      for (int mi = 0; mi < 4; mi++)
        #pragma unroll
        for (int ni = 0; ni < 8; ni++)
          mma_f16(acc[mi][ni], afr[mi][0], afr[mi][1], afr[mi][2], afr[mi][3],
                  bfr[ni][0], bfr[ni][1]);
    }
    st_c = (st_c == 2) ? 0 : st_c + 1;
    st_p = (st_p == 2) ? 0 : st_p + 1;
    __syncthreads();
  }

  #pragma unroll
  for (int mi = 0; mi < 4; mi++) {
    #pragma unroll
    for (int half = 0; half < 2; half++) {
      const int m = bm + wm0 + mi * 16 + g + half * 8;
      const int b = m / NS, s = m % NS;
      #pragma unroll
      for (int ni = 0; ni < 8; ni++) {
        float v0 = acc[mi][ni][half * 2 + 0];
        float v1 = acc[mi][ni][half * 2 + 1];
        const int n = bn + wn0 + ni * 8 + tk * 2;
        if (MODE == 0) {
          float2 vv = {v0, v1};
          *(float2*)&C[(size_t)m * ND + n] = vv;
        } else if (MODE == 3) {
          const int h = n / NDH, d = n % NDH;
          __half* dst = Ch + (((size_t)(b * NH + h)) * NDH + d) * NS + s;
          dst[0]  = __float2half_rn(v0);
          dst[NS] = __float2half_rn(v1);
        } else {  // MODE 2
          const int h = n / NDH, d = n % NDH;
          __half* dst = Ch + (((size_t)(b * NH + h)) * NS + s) * NDH;
          const int pi = d >> 1;
          const float cc = fcos[s * (NDH / 2) + pi];
          const float sn = fsin[s * (NDH / 2) + pi];
          v0 *= outscale; v1 *= outscale;
          __half2 vv = __floats2half2_rn(v0 * cc - v1 * sn, v0 * sn + v1 * cc);
          *(__half2*)&dst[d] = vv;
        }
      }
    }
  }
}

// ============================================================================
// Flash attention (causal), fp16 mma + ldmatrix, cp.async 3-stage K/V ring.
// Br=128 (8 warps x 16 rows), Bc=64. (unchanged from R10)
// ============================================================================
#define FL_QPITCH 68
#define FL_VPITCH 36
#define FL_KWORDS (64 * FL_QPITCH)                 // 4352
#define FL_VWORDS (128 * FL_VPITCH)                // 4608
#define FL_STAGEW (FL_KWORDS + FL_VWORDS)          // 8960
#define FL_SMEM ((128 * FL_QPITCH + 3 * FL_STAGEW) * 4)

__global__ void __launch_bounds__(256) flash_tc(
    const __half* __restrict__ gq, const __half* __restrict__ gk,
    const __half* __restrict__ gvt, __half* __restrict__ ctx)
{
  extern __shared__ unsigned smf[];
  unsigned* Qs = smf;
  unsigned* St = smf + 128 * FL_QPITCH;   // 3 stages

  const int bh = blockIdx.y;
  const int b = bh >> 4, h = bh & 15;
  const int qb = blockIdx.x * 128;
  const int tid = threadIdx.x;
  const int warp = tid >> 5, lane = tid & 31;
  const int g = lane >> 2, tk = lane & 3;
  const int l8 = lane & 7, lm = lane >> 3;
  const int m0 = warp * 16;
  const int qrow_max = qb + m0 + 15;

  const __half* kbase = gk + (size_t)bh * NS * NDH;
  const __half* vtb = gvt + (size_t)bh * NDH * NS;
  const int ntiles = qb / 64 + 2;
  const uint32_t sQs = (uint32_t)__cvta_generic_to_shared(Qs);
  const uint32_t sSt = (uint32_t)__cvta_generic_to_shared(St);

  const uint32_t qoff = sQs +
    (uint32_t)(((m0 + l8 + (lm & 1) * 8) * FL_QPITCH + (lm >> 1) * 4) * 4);
  uint32_t koff[4];
  #pragma unroll
  for (int n2 = 0; n2 < 4; n2++)
    koff[n2] = (uint32_t)(((n2 * 16 + l8 + (lm >> 1) * 8) * FL_QPITCH
                           + (lm & 1) * 4) * 4);
  uint32_t voff[8];
  #pragma unroll
  for (int mi = 0; mi < 8; mi++)
    voff[mi] = (uint32_t)((FL_KWORDS + (mi * 16 + l8 + (lm & 1) * 8) * FL_VPITCH
                           + (lm >> 1) * 4) * 4);

  #define FL_ISSUE(t, s) do { \
    if ((t) < ntiles) { \
      const int k0i = (t) * 64; \
      const uint32_t kd = sSt + (uint32_t)(s) * FL_STAGEW * 4; \
      const uint32_t vd = kd + FL_KWORDS * 4; \
      _Pragma("unroll") \
      for (int i = 0; i < 4; i++) { \
        const int id = tid + 256 * i; \
        const int kr = id >> 4, kc = id & 15; \
        cpasync16(kd + (uint32_t)(kr * FL_QPITCH + kc * 4) * 4, \
                  kbase + (size_t)(k0i + kr) * NDH + kc * 8); \
        const int vr = id >> 3, vc = id & 7; \
        cpasync16(vd + (uint32_t)(vr * FL_VPITCH + vc * 4) * 4, \
                  vtb + (size_t)vr * NS + k0i + vc * 8); \
      } \
    } \
    asm volatile("cp.async.commit_group;" ::); \
  } while (0)

  FL_ISSUE(0, 0);
  FL_ISSUE(1, 1);

  const __half* qbase = gq + ((size_t)bh * NS + qb) * NDH;
  #pragma unroll
  for (int i = 0; i < 8; i++) {
    int idx = i * 256 + tid;
    int row = idx >> 4, c = idx & 15;
    uint4 v = *(const uint4*)(qbase + (size_t)row * NDH + c * 8);
    *(uint4*)(Qs + row * FL_QPITCH + c * 4) = v;
  }

  float oacc[8][2][4];
  #pragma unroll
  for (int mi = 0; mi < 8; mi++)
    #pragma unroll
    for (int nt = 0; nt < 2; nt++)
      #pragma unroll
      for (int c = 0; c < 4; c++) oacc[mi][nt][c] = 0.f;
  float mrow0 = -1e30f, mrow1 = -1e30f, lrow0 = 0.f, lrow1 = 0.f;

  for (int t = 0; t < ntiles; t++) {
    const int k0 = t * 64;
    const int s = t % 3;
    asm volatile("cp.async.wait_group 1;" ::);
    __syncthreads();
    FL_ISSUE(t + 2, (t + 2) % 3);
    if (k0 > qrow_max) continue;

    const uint32_t stb = sSt + (uint32_t)s * FL_STAGEW * 4;

    float sacc[8][4];
    #pragma unroll
    for (int nt = 0; nt < 8; nt++)
      #pragma unroll
      for (int c = 0; c < 4; c++) sacc[nt][c] = 0.f;

    #pragma unroll
    for (int ks = 0; ks < 8; ks++) {
      unsigned a0, a1, a2, a3;
      ldsm4(a0, a1, a2, a3, qoff + ks * 32);
      unsigned kf[8][2];
      #pragma unroll
      for (int n2 = 0; n2 < 4; n2++)
        ldsm4(kf[2 * n2][0], kf[2 * n2][1], kf[2 * n2 + 1][0],
              kf[2 * n2 + 1][1], stb + koff[n2] + ks * 32);
      #pragma unroll
      for (int nt = 0; nt < 8; nt++)
        mma_f16(sacc[nt], a0, a1, a2, a3, kf[nt][0], kf[nt][1]);
    }

    if (k0 + 63 > qb + m0) {
      const int r0q = qb + m0 + g, r1q = r0q + 8;
      #pragma unroll
      for (int nt = 0; nt < 8; nt++) {
        const int key0 = k0 + nt * 8 + 2 * tk;
        if (key0     > r0q) sacc[nt][0] = -1e30f;
        if (key0 + 1 > r0q) sacc[nt][1] = -1e30f;
        if (key0     > r1q) sacc[nt][2] = -1e30f;
        if (key0 + 1 > r1q) sacc[nt][3] = -1e30f;
      }
    }

    float mx0 = mrow0, mx1 = mrow1;
    #pragma unroll
    for (int nt = 0; nt < 8; nt++) {
      mx0 = fmaxf(mx0, fmaxf(sacc[nt][0], sacc[nt][1]));
      mx1 = fmaxf(mx1, fmaxf(sacc[nt][2], sacc[nt][3]));
    }
    mx0 = fmaxf(mx0, __shfl_xor_sync(0xffffffffu, mx0, 1));
    mx0 = fmaxf(mx0, __shfl_xor_sync(0xffffffffu, mx0, 2));
    mx1 = fmaxf(mx1, __shfl_xor_sync(0xffffffffu, mx1, 1));
    mx1 = fmaxf(mx1, __shfl_xor_sync(0xffffffffu, mx1, 2));
    const float al0 = __expf(mrow0 - mx0);
    const float al1 = __expf(mrow1 - mx1);
    mrow0 = mx0; mrow1 = mx1;
    lrow0 *= al0; lrow1 *= al1;

    const float af00 = __shfl_sync(0xffffffffu, al0, 8 * tk);
    const float af01 = __shfl_sync(0xffffffffu, al0, 8 * tk + 4);
    const float af10 = __shfl_sync(0xffffffffu, al1, 8 * tk);
    const float af11 = __shfl_sync(0xffffffffu, al1, 8 * tk + 4);
    #pragma unroll
    for (int mi = 0; mi < 8; mi++) {
      oacc[mi][0][0] *= af00; oacc[mi][0][1] *= af01;
      oacc[mi][0][2] *= af00; oacc[mi][0][3] *= af01;
      oacc[mi][1][0] *= af10; oacc[mi][1][1] *= af11;
      oacc[mi][1][2] *= af10; oacc[mi][1][3] *= af11;
    }

    float cb0 = 0.f, cb1 = 0.f;
    #pragma unroll
    for (int nt = 0; nt < 8; nt++) {
      sacc[nt][0] = __expf(sacc[nt][0] - mx0);
      sacc[nt][1] = __expf(sacc[nt][1] - mx0);
      sacc[nt][2] = __expf(sacc[nt][2] - mx1);
      sacc[nt][3] = __expf(sacc[nt][3] - mx1);
      cb0 += sacc[nt][0] + sacc[nt][1];
      cb1 += sacc[nt][2] + sacc[nt][3];
    }
    cb0 += __shfl_xor_sync(0xffffffffu, cb0, 1);
    cb0 += __shfl_xor_sync(0xffffffffu, cb0, 2);
    cb1 += __shfl_xor_sync(0xffffffffu, cb1, 1);
    cb1 += __shfl_xor_sync(0xffffffffu, cb1, 2);
    lrow0 += cb0; lrow1 += cb1;

    #pragma unroll
    for (int ks = 0; ks < 4; ks++) {
      const unsigned bl0 = packh2(sacc[2 * ks][0],     sacc[2 * ks][1]);
      const unsigned bl1 = packh2(sacc[2 * ks + 1][0], sacc[2 * ks + 1][1]);
      const unsigned bh0 = packh2(sacc[2 * ks][2],     sacc[2 * ks][3]);
      const unsigned bh1 = packh2(sacc[2 * ks + 1][2], sacc[2 * ks + 1][3]);
      #pragma unroll
      for (int mi = 0; mi < 8; mi++) {
        unsigned va0, va1, va2, va3;
        ldsm4(va0, va1, va2, va3, stb + voff[mi] + ks * 32);
        mma_f16(oacc[mi][0], va0, va1, va2, va3, bl0, bl1);
        mma_f16(oacc[mi][1], va0, va1, va2, va3, bh0, bh1);
      }
    }
  }

  const float l00 = __shfl_sync(0xffffffffu, lrow0, 8 * tk);
  const float l01 = __shfl_sync(0xffffffffu, lrow0, 8 * tk + 4);
  const float l10 = __shfl_sync(0xffffffffu, lrow1, 8 * tk);
  const float l11 = __shfl_sync(0xffffffffu, lrow1, 8 * tk + 4);
  const float i00 = 1.f / l00, i01 = 1.f / l01;
  const float i10 = 1.f / l10, i11 = 1.f / l11;

  __half* cp = ctx + ((size_t)(b * NS + qb + m0)) * ND + h * NDH;
  #pragma unroll
  for (int mi = 0; mi < 8; mi++) {
    const int d0 = mi * 16 + g;
    cp[(size_t)(2 * tk) * ND + d0]         = __float2half_rn(oacc[mi][0][0] * i00);
    cp[(size_t)(2 * tk + 1) * ND + d0]     = __float2half_rn(oacc[mi][0][1] * i01);
    cp[(size_t)(2 * tk) * ND + d0 + 8]     = __float2half_rn(oacc[mi][0][2] * i00);
    cp[(size_t)(2 * tk + 1) * ND + d0 + 8] = __float2half_rn(oacc[mi][0][3] * i01);
    cp[(size_t)(8 + 2 * tk) * ND + d0]     = __float2half_rn(oacc[mi][1][0] * i10);
    cp[(size_t)(9 + 2 * tk) * ND + d0]     = __float2half_rn(oacc[mi][1][1] * i11);
    cp[(size_t)(8 + 2 * tk) * ND + d0 + 8] = __float2half_rn(oacc[mi][1][2] * i10);
    cp[(size_t)(9 + 2 * tk) * ND + d0 + 8] = __float2half_rn(oacc[mi][1][3] * i11);
  }
}

extern "C" void kernel_launch(void* const* d_in, const int* in_sizes, int n_in,
                              void* d_out, int out_size) {
  const float* x  = (const float*)d_in[0];
  const float* fc = (const float*)d_in[1];
  const float* fs = (const float*)d_in[2];
  // d_in[3] is the mask; causal handled analytically
  const float* wq = (const float*)d_in[4];
  const float* wk = (const float*)d_in[5];
  const float* wv = (const float*)d_in[6];
  const float* wo = (const float*)d_in[7];

  __half *qh, *kh, *vt, *ctx, *xh, *wqh, *wkh, *wvh, *woh;
  cudaGetSymbolAddress((void**)&qh,  g_qh);
  cudaGetSymbolAddress((void**)&kh,  g_kh);
  cudaGetSymbolAddress((void**)&vt,  g_vt);
  cudaGetSymbolAddress((void**)&ctx, g_ctx);
  cudaGetSymbolAddress((void**)&xh,  g_xh);
  cudaGetSymbolAddress((void**)&wqh, g_wqh);
  cudaGetSymbolAddress((void**)&wkh, g_wkh);
  cudaGetSymbolAddress((void**)&wvh, g_wvh);
  cudaGetSymbolAddress((void**)&woh, g_woh);

  cudaFuncSetAttribute(flash_tc, cudaFuncAttributeMaxDynamicSharedMemorySize, FL_SMEM);
  cudaFuncSetAttribute(gemm_h<0>, cudaFuncAttributeMaxDynamicSharedMemorySize, GH_SMEM);
  cudaFuncSetAttribute(gemm_h<2>, cudaFuncAttributeMaxDynamicSharedMemorySize, GH_SMEM);
  cudaFuncSetAttribute(gemm_h<3>, cudaFuncAttributeMaxDynamicSharedMemorySize, GH_SMEM);

  // Prep: convert x + all 4 weights to fp16 (2 launches).
  const int nx4 = NM * ND / 4;
  tohalf_k<<<nx4 / 256, 256>>>(x, xh, nx4);
  tohalf4_k<<<4 * (ND * ND / 4) / 256, 256>>>(wq, wk, wv, wo, wqh, wkh, wvh, woh);

  const float scale = 0.08838834764831845f;  // 1/sqrt(128)
  dim3 gg(ND / 128, NM / 256);
  gemm_h<2><<<gg, 256, GH_SMEM>>>(xh, wqh, nullptr, qh, fc, fs, scale);
  gemm_h<2><<<gg, 256, GH_SMEM>>>(xh, wkh, nullptr, kh, fc, fs, 1.0f);
  gemm_h<3><<<gg, 256, GH_SMEM>>>(xh, wvh, nullptr, vt, nullptr, nullptr, 1.0f);

  dim3 fg(NS / 128, NB * NH);
  flash_tc<<<fg, 256, FL_SMEM>>>(qh, kh, vt, ctx);

  gemm_h<0><<<gg, 256, GH_SMEM>>>(ctx, woh, (float*)d_out, nullptr, nullptr, nullptr, 1.0f);
}

// round 12
// speedup vs baseline: 1.1719x; 1.1719x over previous
#include <cuda_runtime.h>
#include <cuda_fp16.h>
#include <stdint.h>
#include <math.h>

#define NB 2
#define NS 2048
#define ND 2048
#define NH 16
#define NDH 128
#define NM (NB*NS)

// Scratch (device globals; no allocation allowed)
__device__ __half g_qh[(size_t)NB*NH*NS*NDH];
__device__ __half g_kh[(size_t)NB*NH*NS*NDH];
__device__ __half g_vt[(size_t)NB*NH*NDH*NS];   // V transposed: [b,h,dh,s] fp16
__device__ __half g_ctx[(size_t)NB*NS*ND];      // attention output, fp16
__device__ __half g_xh[(size_t)NM*ND];          // x in fp16
__device__ __half g_wqh[(size_t)ND*ND];
__device__ __half g_wkh[(size_t)ND*ND];
__device__ __half g_wvh[(size_t)ND*ND];
__device__ __half g_woh[(size_t)ND*ND];

__device__ __forceinline__ unsigned packh2(float lo, float hi) {
  __half2 h = __floats2half2_rn(lo, hi);
  return *(unsigned*)&h;
}
__device__ __forceinline__ void mma_f16(float* c, unsigned a0, unsigned a1,
                                        unsigned a2, unsigned a3,
                                        unsigned b0, unsigned b1) {
  asm volatile(
    "mma.sync.aligned.m16n8k16.row.col.f32.f16.f16.f32 "
    "{%0,%1,%2,%3},{%4,%5,%6,%7},{%8,%9},{%0,%1,%2,%3};\n"
    : "+f"(c[0]), "+f"(c[1]), "+f"(c[2]), "+f"(c[3])
    : "r"(a0), "r"(a1), "r"(a2), "r"(a3), "r"(b0), "r"(b1));
}
__device__ __forceinline__ void ldsm4(unsigned& r0, unsigned& r1,
                                      unsigned& r2, unsigned& r3,
                                      uint32_t addr) {
  asm volatile(
    "ldmatrix.sync.aligned.m8n8.x4.shared.b16 {%0,%1,%2,%3}, [%4];"
    : "=r"(r0), "=r"(r1), "=r"(r2), "=r"(r3) : "r"(addr));
}
__device__ __forceinline__ void cpasync16(uint32_t dst, const void* src) {
  asm volatile("cp.async.cg.shared.global [%0], [%1], 16;" :: "r"(dst),
               "l"(src));
}

// fp32 -> fp16 conversion, vectorized.
__global__ void tohalf_k(const float* __restrict__ src,
                         __half* __restrict__ dst, int n4) {
  int i = blockIdx.x * 256 + threadIdx.x;
  if (i < n4) {
    float4 v = ((const float4*)src)[i];
    __half2 h0 = __floats2half2_rn(v.x, v.y);
    __half2 h1 = __floats2half2_rn(v.z, v.w);
    uint2 u = {*(unsigned*)&h0, *(unsigned*)&h1};
    ((uint2*)dst)[i] = u;
  }
}

// 4 weight matrices (ND*ND each) in one launch.
__global__ void tohalf4_k(const float* __restrict__ s0, const float* __restrict__ s1,
                          const float* __restrict__ s2, const float* __restrict__ s3,
                          __half* __restrict__ d0, __half* __restrict__ d1,
                          __half* __restrict__ d2, __half* __restrict__ d3) {
  const int per = (ND * ND / 4) / 256;       // blocks per tensor
  const int which = blockIdx.x / per;
  const int i = (blockIdx.x % per) * 256 + threadIdx.x;
  const float* src = (which == 0) ? s0 : (which == 1) ? s1 : (which == 2) ? s2 : s3;
  __half* dst = (which == 0) ? d0 : (which == 1) ? d1 : (which == 2) ? d2 : d3;
  float4 v = ((const float4*)src)[i];
  __half2 h0 = __floats2half2_rn(v.x, v.y);
  __half2 h1 = __floats2half2_rn(v.z, v.w);
  uint2 u = {*(unsigned*)&h0, *(unsigned*)&h1};
  ((uint2*)dst)[i] = u;
}

// ============================================================================
// GEMM: fp16 mma.sync + ldmatrix, cp.async 3-stage, block 128x128,
// K-tile 64, warp tile 64x32 (8 warps, 2x4), 2 CTA/SM.
// ONE __syncthreads per K-tile (the ring makes the second barrier redundant:
// sync at iteration kt+1 orders all compute(kt) before issue into stage kt%3).
// Smem rows: 64 halves = 32 words, pitch 36 (ldmatrix phases conflict-free:
// banks 4*l8 distinct).
// ============================================================================
#define GK_STAGEW 4608                 // 128 rows * 36 words
#define GH_SMEM (3 * 2 * GK_STAGEW * 4)

template<int MODE>
__global__ void __launch_bounds__(256, 2) gemm_h(
    const __half* __restrict__ A, const __half* __restrict__ W,
    float* __restrict__ C, __half* __restrict__ Ch,
    const float* __restrict__ fcos, const float* __restrict__ fsin,
    float outscale)
{
  extern __shared__ unsigned smh[];
  unsigned* As = smh;                    // [3][128][36]
  unsigned* Bs = smh + 3 * GK_STAGEW;
  const int K = ND;
  const int bm = blockIdx.y * 128;
  const int bn = blockIdx.x * 128;
  const int tid = threadIdx.x;
  const int warp = tid >> 5, lane = tid & 31;
  const int wm0 = (warp >> 2) * 64;
  const int wn0 = (warp & 3) * 32;
  const int g = lane >> 2, tk = lane & 3;
  const int l8 = lane & 7, lm = lane >> 3;   // ldmatrix: row-in-8x8, matrix id

  const uint32_t sa = (uint32_t)__cvta_generic_to_shared(As);
  const uint32_t sbm = (uint32_t)__cvta_generic_to_shared(Bs);

  // Per-thread ldmatrix byte offsets within a stage (add ks*32 for k16 steps).
  uint32_t aoff[4];
  #pragma unroll
  for (int mi = 0; mi < 4; mi++)
    aoff[mi] = (uint32_t)(((wm0 + mi * 16 + l8 + (lm & 1) * 8) * 36
                           + (lm >> 1) * 4) * 4);
  uint32_t boff[2];
  #pragma unroll
  for (int n2 = 0; n2 < 2; n2++)
    boff[n2] = (uint32_t)(((wn0 + n2 * 16 + l8 + (lm >> 1) * 8) * 36
                           + (lm & 1) * 4) * 4);

  float acc[4][4][4];
  #pragma unroll
  for (int mi = 0; mi < 4; mi++)
    #pragma unroll
    for (int ni = 0; ni < 4; ni++)
      #pragma unroll
      for (int cc = 0; cc < 4; cc++) acc[mi][ni][cc] = 0.f;

  // copy: 1024 16B-chunks per matrix per tile; 4 per thread each.
  #define GH_ISSUE(kt, st) do { \
    _Pragma("unroll") \
    for (int i = 0; i < 4; i++) { \
      const int id = tid + 256 * i; \
      const int r = id >> 3, c = id & 7; \
      const uint32_t wo = (uint32_t)((st) * GK_STAGEW + r * 36 + c * 4) * 4; \
      cpasync16(sa + wo, A + (size_t)(bm + r) * K + (kt) * 64 + c * 8); \
      cpasync16(sbm + wo, W + (size_t)(bn + r) * K + (kt) * 64 + c * 8); \
    } \
    asm volatile("cp.async.commit_group;" ::); \
  } while (0)

  GH_ISSUE(0, 0);
  GH_ISSUE(1, 1);

  const int niter = K / 64;   // 32
  int st_c = 0, st_p = 2;
  for (int kt = 0; kt < niter; kt++) {
    asm volatile("cp.async.wait_group 1;" ::);
    __syncthreads();
    if (kt + 2 < niter) GH_ISSUE(kt + 2, st_p);
    else asm volatile("cp.async.commit_group;" ::);

    const uint32_t ab = sa + (uint32_t)st_c * GK_STAGEW * 4;
    const uint32_t bb = sbm + (uint32_t)st_c * GK_STAGEW * 4;
    #pragma unroll
    for (int ks = 0; ks < 4; ks++) {
      unsigned afr[4][4], bfr[4][2];
      #pragma unroll
      for (int mi = 0; mi < 4; mi++)
        ldsm4(afr[mi][0], afr[mi][1], afr[mi][2], afr[mi][3],
              ab + aoff[mi] + ks * 32);
      #pragma unroll
      for (int n2 = 0; n2 < 2; n2++)
        ldsm4(bfr[2 * n2][0], bfr[2 * n2][1], bfr[2 * n2 + 1][0],
              bfr[2 * n2 + 1][1], bb + boff[n2] + ks * 32);
      #pragma unroll
      for (int mi = 0; mi < 4; mi++)
        #pragma unroll
        for (int ni = 0; ni < 4; ni++)
          mma_f16(acc[mi][ni], afr[mi][0], afr[mi][1], afr[mi][2], afr[mi][3],
                  bfr[ni][0], bfr[ni][1]);
    }
    st_c = (st_c == 2) ? 0 : st_c + 1;
    st_p = (st_p == 2) ? 0 : st_p + 1;
  }

  #pragma unroll
  for (int mi = 0; mi < 4; mi++) {
    #pragma unroll
    for (int half = 0; half < 2; half++) {
      const int m = bm + wm0 + mi * 16 + g + half * 8;
      const int b = m / NS, s = m % NS;
      #pragma unroll
      for (int ni = 0; ni < 4; ni++) {
        float v0 = acc[mi][ni][half * 2 + 0];
        float v1 = acc[mi][ni][half * 2 + 1];
        const int n = bn + wn0 + ni * 8 + tk * 2;
        if (MODE == 0) {
          float2 vv = {v0, v1};
          *(float2*)&C[(size_t)m * ND + n] = vv;
        } else if (MODE == 3) {
          const int h = n / NDH, d = n % NDH;
          __half* dst = Ch + (((size_t)(b * NH + h)) * NDH + d) * NS + s;
          dst[0]  = __float2half_rn(v0);
          dst[NS] = __float2half_rn(v1);
        } else {  // MODE 2
          const int h = n / NDH, d = n % NDH;
          __half* dst = Ch + (((size_t)(b * NH + h)) * NS + s) * NDH;
          const int pi = d >> 1;
          const float cc = fcos[s * (NDH / 2) + pi];
          const float sn = fsin[s * (NDH / 2) + pi];
          v0 *= outscale; v1 *= outscale;
          __half2 vv = __floats2half2_rn(v0 * cc - v1 * sn, v0 * sn + v1 * cc);
          *(__half2*)&dst[d] = vv;
        }
      }
    }
  }
}

// ============================================================================
// Flash attention (causal), fp16 mma + ldmatrix, cp.async 3-stage K/V ring.
// Br=128 (8 warps x 16 rows), Bc=64. (unchanged from R10)
// ============================================================================
#define FL_QPITCH 68
#define FL_VPITCH 36
#define FL_KWORDS (64 * FL_QPITCH)                 // 4352
#define FL_VWORDS (128 * FL_VPITCH)                // 4608
#define FL_STAGEW (FL_KWORDS + FL_VWORDS)          // 8960
#define FL_SMEM ((128 * FL_QPITCH + 3 * FL_STAGEW) * 4)

__global__ void __launch_bounds__(256) flash_tc(
    const __half* __restrict__ gq, const __half* __restrict__ gk,
    const __half* __restrict__ gvt, __half* __restrict__ ctx)
{
  extern __shared__ unsigned smf[];
  unsigned* Qs = smf;
  unsigned* St = smf + 128 * FL_QPITCH;   // 3 stages

  const int bh = blockIdx.y;
  const int b = bh >> 4, h = bh & 15;
  const int qb = blockIdx.x * 128;
  const int tid = threadIdx.x;
  const int warp = tid >> 5, lane = tid & 31;
  const int g = lane >> 2, tk = lane & 3;
  const int l8 = lane & 7, lm = lane >> 3;
  const int m0 = warp * 16;
  const int qrow_max = qb + m0 + 15;

  const __half* kbase = gk + (size_t)bh * NS * NDH;
  const __half* vtb = gvt + (size_t)bh * NDH * NS;
  const int ntiles = qb / 64 + 2;
  const uint32_t sQs = (uint32_t)__cvta_generic_to_shared(Qs);
  const uint32_t sSt = (uint32_t)__cvta_generic_to_shared(St);

  const uint32_t qoff = sQs +
    (uint32_t)(((m0 + l8 + (lm & 1) * 8) * FL_QPITCH + (lm >> 1) * 4) * 4);
  uint32_t koff[4];
  #pragma unroll
  for (int n2 = 0; n2 < 4; n2++)
    koff[n2] = (uint32_t)(((n2 * 16 + l8 + (lm >> 1) * 8) * FL_QPITCH
                           + (lm & 1) * 4) * 4);
  uint32_t voff[8];
  #pragma unroll
  for (int mi = 0; mi < 8; mi++)
    voff[mi] = (uint32_t)((FL_KWORDS + (mi * 16 + l8 + (lm & 1) * 8) * FL_VPITCH
                           + (lm >> 1) * 4) * 4);

  #define FL_ISSUE(t, s) do { \
    if ((t) < ntiles) { \
      const int k0i = (t) * 64; \
      const uint32_t kd = sSt + (uint32_t)(s) * FL_STAGEW * 4; \
      const uint32_t vd = kd + FL_KWORDS * 4; \
      _Pragma("unroll") \
      for (int i = 0; i < 4; i++) { \
        const int id = tid + 256 * i; \
        const int kr = id >> 4, kc = id & 15; \
        cpasync16(kd + (uint32_t)(kr * FL_QPITCH + kc * 4) * 4, \
                  kbase + (size_t)(k0i + kr) * NDH + kc * 8); \
        const int vr = id >> 3, vc = id & 7; \
        cpasync16(vd + (uint32_t)(vr * FL_VPITCH + vc * 4) * 4, \
                  vtb + (size_t)vr * NS + k0i + vc * 8); \
      } \
    } \
    asm volatile("cp.async.commit_group;" ::); \
  } while (0)

  FL_ISSUE(0, 0);
  FL_ISSUE(1, 1);

  const __half* qbase = gq + ((size_t)bh * NS + qb) * NDH;
  #pragma unroll
  for (int i = 0; i < 8; i++) {
    int idx = i * 256 + tid;
    int row = idx >> 4, c = idx & 15;
    uint4 v = *(const uint4*)(qbase + (size_t)row * NDH + c * 8);
    *(uint4*)(Qs + row * FL_QPITCH + c * 4) = v;
  }

  float oacc[8][2][4];
  #pragma unroll
  for (int mi = 0; mi < 8; mi++)
    #pragma unroll
    for (int nt = 0; nt < 2; nt++)
      #pragma unroll
      for (int c = 0; c < 4; c++) oacc[mi][nt][c] = 0.f;
  float mrow0 = -1e30f, mrow1 = -1e30f, lrow0 = 0.f, lrow1 = 0.f;

  for (int t = 0; t < ntiles; t++) {
    const int k0 = t * 64;
    const int s = t % 3;
    asm volatile("cp.async.wait_group 1;" ::);
    __syncthreads();
    FL_ISSUE(t + 2, (t + 2) % 3);
    if (k0 > qrow_max) continue;

    const uint32_t stb = sSt + (uint32_t)s * FL_STAGEW * 4;

    float sacc[8][4];
    #pragma unroll
    for (int nt = 0; nt < 8; nt++)
      #pragma unroll
      for (int c = 0; c < 4; c++) sacc[nt][c] = 0.f;

    #pragma unroll
    for (int ks = 0; ks < 8; ks++) {
      unsigned a0, a1, a2, a3;
      ldsm4(a0, a1, a2, a3, qoff + ks * 32);
      unsigned kf[8][2];
      #pragma unroll
      for (int n2 = 0; n2 < 4; n2++)
        ldsm4(kf[2 * n2][0], kf[2 * n2][1], kf[2 * n2 + 1][0],
              kf[2 * n2 + 1][1], stb + koff[n2] + ks * 32);
      #pragma unroll
      for (int nt = 0; nt < 8; nt++)
        mma_f16(sacc[nt], a0, a1, a2, a3, kf[nt][0], kf[nt][1]);
    }

    if (k0 + 63 > qb + m0) {
      const int r0q = qb + m0 + g, r1q = r0q + 8;
      #pragma unroll
      for (int nt = 0; nt < 8; nt++) {
        const int key0 = k0 + nt * 8 + 2 * tk;
        if (key0     > r0q) sacc[nt][0] = -1e30f;
        if (key0 + 1 > r0q) sacc[nt][1] = -1e30f;
        if (key0     > r1q) sacc[nt][2] = -1e30f;
        if (key0 + 1 > r1q) sacc[nt][3] = -1e30f;
      }
    }

    float mx0 = mrow0, mx1 = mrow1;
    #pragma unroll
    for (int nt = 0; nt < 8; nt++) {
      mx0 = fmaxf(mx0, fmaxf(sacc[nt][0], sacc[nt][1]));
      mx1 = fmaxf(mx1, fmaxf(sacc[nt][2], sacc[nt][3]));
    }
    mx0 = fmaxf(mx0, __shfl_xor_sync(0xffffffffu, mx0, 1));
    mx0 = fmaxf(mx0, __shfl_xor_sync(0xffffffffu, mx0, 2));
    mx1 = fmaxf(mx1, __shfl_xor_sync(0xffffffffu, mx1, 1));
    mx1 = fmaxf(mx1, __shfl_xor_sync(0xffffffffu, mx1, 2));
    const float al0 = __expf(mrow0 - mx0);
    const float al1 = __expf(mrow1 - mx1);
    mrow0 = mx0; mrow1 = mx1;
    lrow0 *= al0; lrow1 *= al1;

    const float af00 = __shfl_sync(0xffffffffu, al0, 8 * tk);
    const float af01 = __shfl_sync(0xffffffffu, al0, 8 * tk + 4);
    const float af10 = __shfl_sync(0xffffffffu, al1, 8 * tk);
    const float af11 = __shfl_sync(0xffffffffu, al1, 8 * tk + 4);
    #pragma unroll
    for (int mi = 0; mi < 8; mi++) {
      oacc[mi][0][0] *= af00; oacc[mi][0][1] *= af01;
      oacc[mi][0][2] *= af00; oacc[mi][0][3] *= af01;
      oacc[mi][1][0] *= af10; oacc[mi][1][1] *= af11;
      oacc[mi][1][2] *= af10; oacc[mi][1][3] *= af11;
    }

    float cb0 = 0.f, cb1 = 0.f;
    #pragma unroll
    for (int nt = 0; nt < 8; nt++) {
      sacc[nt][0] = __expf(sacc[nt][0] - mx0);
      sacc[nt][1] = __expf(sacc[nt][1] - mx0);
      sacc[nt][2] = __expf(sacc[nt][2] - mx1);
      sacc[nt][3] = __expf(sacc[nt][3] - mx1);
      cb0 += sacc[nt][0] + sacc[nt][1];
      cb1 += sacc[nt][2] + sacc[nt][3];
    }
    cb0 += __shfl_xor_sync(0xffffffffu, cb0, 1);
    cb0 += __shfl_xor_sync(0xffffffffu, cb0, 2);
    cb1 += __shfl_xor_sync(0xffffffffu, cb1, 1);
    cb1 += __shfl_xor_sync(0xffffffffu, cb1, 2);
    lrow0 += cb0; lrow1 += cb1;

    #pragma unroll
    for (int ks = 0; ks < 4; ks++) {
      const unsigned bl0 = packh2(sacc[2 * ks][0],     sacc[2 * ks][1]);
      const unsigned bl1 = packh2(sacc[2 * ks + 1][0], sacc[2 * ks + 1][1]);
      const unsigned bh0 = packh2(sacc[2 * ks][2],     sacc[2 * ks][3]);
      const unsigned bh1 = packh2(sacc[2 * ks + 1][2], sacc[2 * ks + 1][3]);
      #pragma unroll
      for (int mi = 0; mi < 8; mi++) {
        unsigned va0, va1, va2, va3;
        ldsm4(va0, va1, va2, va3, stb + voff[mi] + ks * 32);
        mma_f16(oacc[mi][0], va0, va1, va2, va3, bl0, bl1);
        mma_f16(oacc[mi][1], va0, va1, va2, va3, bh0, bh1);
      }
    }
  }

  const float l00 = __shfl_sync(0xffffffffu, lrow0, 8 * tk);
  const float l01 = __shfl_sync(0xffffffffu, lrow0, 8 * tk + 4);
  const float l10 = __shfl_sync(0xffffffffu, lrow1, 8 * tk);
  const float l11 = __shfl_sync(0xffffffffu, lrow1, 8 * tk + 4);
  const float i00 = 1.f / l00, i01 = 1.f / l01;
  const float i10 = 1.f / l10, i11 = 1.f / l11;

  __half* cp = ctx + ((size_t)(b * NS + qb + m0)) * ND + h * NDH;
  #pragma unroll
  for (int mi = 0; mi < 8; mi++) {
    const int d0 = mi * 16 + g;
    cp[(size_t)(2 * tk) * ND + d0]         = __float2half_rn(oacc[mi][0][0] * i00);
    cp[(size_t)(2 * tk + 1) * ND + d0]     = __float2half_rn(oacc[mi][0][1] * i01);
    cp[(size_t)(2 * tk) * ND + d0 + 8]     = __float2half_rn(oacc[mi][0][2] * i00);
    cp[(size_t)(2 * tk + 1) * ND + d0 + 8] = __float2half_rn(oacc[mi][0][3] * i01);
    cp[(size_t)(8 + 2 * tk) * ND + d0]     = __float2half_rn(oacc[mi][1][0] * i10);
    cp[(size_t)(9 + 2 * tk) * ND + d0]     = __float2half_rn(oacc[mi][1][1] * i11);
    cp[(size_t)(8 + 2 * tk) * ND + d0 + 8] = __float2half_rn(oacc[mi][1][2] * i10);
    cp[(size_t)(9 + 2 * tk) * ND + d0 + 8] = __float2half_rn(oacc[mi][1][3] * i11);
  }
}

extern "C" void kernel_launch(void* const* d_in, const int* in_sizes, int n_in,
                              void* d_out, int out_size) {
  const float* x  = (const float*)d_in[0];
  const float* fc = (const float*)d_in[1];
  const float* fs = (const float*)d_in[2];
  // d_in[3] is the mask; causal handled analytically
  const float* wq = (const float*)d_in[4];
  const float* wk = (const float*)d_in[5];
  const float* wv = (const float*)d_in[6];
  const float* wo = (const float*)d_in[7];

  __half *qh, *kh, *vt, *ctx, *xh, *wqh, *wkh, *wvh, *woh;
  cudaGetSymbolAddress((void**)&qh,  g_qh);
  cudaGetSymbolAddress((void**)&kh,  g_kh);
  cudaGetSymbolAddress((void**)&vt,  g_vt);
  cudaGetSymbolAddress((void**)&ctx, g_ctx);
  cudaGetSymbolAddress((void**)&xh,  g_xh);
  cudaGetSymbolAddress((void**)&wqh, g_wqh);
  cudaGetSymbolAddress((void**)&wkh, g_wkh);
  cudaGetSymbolAddress((void**)&wvh, g_wvh);
  cudaGetSymbolAddress((void**)&woh, g_woh);

  cudaFuncSetAttribute(flash_tc, cudaFuncAttributeMaxDynamicSharedMemorySize, FL_SMEM);
  cudaFuncSetAttribute(gemm_h<0>, cudaFuncAttributeMaxDynamicSharedMemorySize, GH_SMEM);
  cudaFuncSetAttribute(gemm_h<2>, cudaFuncAttributeMaxDynamicSharedMemorySize, GH_SMEM);
  cudaFuncSetAttribute(gemm_h<3>, cudaFuncAttributeMaxDynamicSharedMemorySize, GH_SMEM);

  // Prep: convert x + all 4 weights to fp16 (2 launches).
  const int nx4 = NM * ND / 4;
  tohalf_k<<<nx4 / 256, 256>>>(x, xh, nx4);
  tohalf4_k<<<4 * (ND * ND / 4) / 256, 256>>>(wq, wk, wv, wo, wqh, wkh, wvh, woh);

  const float scale = 0.08838834764831845f;  // 1/sqrt(128)
  dim3 gg(ND / 128, NM / 128);
  gemm_h<2><<<gg, 256, GH_SMEM>>>(xh, wqh, nullptr, qh, fc, fs, scale);
  gemm_h<2><<<gg, 256, GH_SMEM>>>(xh, wkh, nullptr, kh, fc, fs, 1.0f);
  gemm_h<3><<<gg, 256, GH_SMEM>>>(xh, wvh, nullptr, vt, nullptr, nullptr, 1.0f);

  dim3 fg(NS / 128, NB * NH);
  flash_tc<<<fg, 256, FL_SMEM>>>(qh, kh, vt, ctx);

  gemm_h<0><<<gg, 256, GH_SMEM>>>(ctx, woh, (float*)d_out, nullptr, nullptr, nullptr, 1.0f);
}

// round 13
// speedup vs baseline: 1.2365x; 1.0551x over previous
#include <cuda_runtime.h>
#include <cuda_fp16.h>
#include <stdint.h>
#include <math.h>

#define NB 2
#define NS 2048
#define ND 2048
#define NH 16
#define NDH 128
#define NM (NB*NS)

// Scratch (device globals; no allocation allowed)
__device__ __half g_qh[(size_t)NB*NH*NS*NDH];
__device__ __half g_kh[(size_t)NB*NH*NS*NDH];
__device__ __half g_vt[(size_t)NB*NH*NDH*NS];   // V transposed: [b,h,dh,s] fp16
__device__ __half g_ctx[(size_t)NB*NS*ND];      // attention output, fp16
__device__ __half g_xh[(size_t)NM*ND];          // x in fp16
__device__ __half g_wqh[(size_t)ND*ND];
__device__ __half g_wkh[(size_t)ND*ND];
__device__ __half g_wvh[(size_t)ND*ND];
__device__ __half g_woh[(size_t)ND*ND];

__device__ __forceinline__ unsigned packh2(float lo, float hi) {
  __half2 h = __floats2half2_rn(lo, hi);
  return *(unsigned*)&h;
}
__device__ __forceinline__ void mma_f16(float* c, unsigned a0, unsigned a1,
                                        unsigned a2, unsigned a3,
                                        unsigned b0, unsigned b1) {
  asm volatile(
    "mma.sync.aligned.m16n8k16.row.col.f32.f16.f16.f32 "
    "{%0,%1,%2,%3},{%4,%5,%6,%7},{%8,%9},{%0,%1,%2,%3};\n"
    : "+f"(c[0]), "+f"(c[1]), "+f"(c[2]), "+f"(c[3])
    : "r"(a0), "r"(a1), "r"(a2), "r"(a3), "r"(b0), "r"(b1));
}
__device__ __forceinline__ void ldsm4(unsigned& r0, unsigned& r1,
                                      unsigned& r2, unsigned& r3,
                                      uint32_t addr) {
  asm volatile(
    "ldmatrix.sync.aligned.m8n8.x4.shared.b16 {%0,%1,%2,%3}, [%4];"
    : "=r"(r0), "=r"(r1), "=r"(r2), "=r"(r3) : "r"(addr));
}
__device__ __forceinline__ void cpasync16(uint32_t dst, const void* src) {
  asm volatile("cp.async.cg.shared.global [%0], [%1], 16;" :: "r"(dst),
               "l"(src));
}

// fp32 -> fp16 conversion, vectorized.
__global__ void tohalf_k(const float* __restrict__ src,
                         __half* __restrict__ dst, int n4) {
  int i = blockIdx.x * 256 + threadIdx.x;
  if (i < n4) {
    float4 v = ((const float4*)src)[i];
    __half2 h0 = __floats2half2_rn(v.x, v.y);
    __half2 h1 = __floats2half2_rn(v.z, v.w);
    uint2 u = {*(unsigned*)&h0, *(unsigned*)&h1};
    ((uint2*)dst)[i] = u;
  }
}

// 4 weight matrices (ND*ND each) in one launch.
__global__ void tohalf4_k(const float* __restrict__ s0, const float* __restrict__ s1,
                          const float* __restrict__ s2, const float* __restrict__ s3,
                          __half* __restrict__ d0, __half* __restrict__ d1,
                          __half* __restrict__ d2, __half* __restrict__ d3) {
  const int per = (ND * ND / 4) / 256;       // blocks per tensor
  const int which = blockIdx.x / per;
  const int i = (blockIdx.x % per) * 256 + threadIdx.x;
  const float* src = (which == 0) ? s0 : (which == 1) ? s1 : (which == 2) ? s2 : s3;
  __half* dst = (which == 0) ? d0 : (which == 1) ? d1 : (which == 2) ? d2 : d3;
  float4 v = ((const float4*)src)[i];
  __half2 h0 = __floats2half2_rn(v.x, v.y);
  __half2 h1 = __floats2half2_rn(v.z, v.w);
  uint2 u = {*(unsigned*)&h0, *(unsigned*)&h1};
  ((uint2*)dst)[i] = u;
}

// ============================================================================
// GEMM core config (R12): fp16 mma.sync + ldmatrix, cp.async 3-stage,
// block 128x128, K-tile 64, warp tile 64x32 (8 warps 2x4), 2 CTA/SM,
// one __syncthreads per K-tile. Smem rows: 32 words, pitch 36.
// ============================================================================
#define GK_STAGEW 4608                 // 128 rows * 36 words
#define GH_SMEM (3 * 2 * GK_STAGEW * 4)

// Shared mainloop: computes acc for this block's 128x128 tile.
__device__ __forceinline__ void gemm_mainloop(
    const __half* __restrict__ A, const __half* __restrict__ W,
    int bm, int bn, unsigned* smh, float acc[4][4][4],
    uint32_t* aoff, uint32_t* boff)
{
  const int K = ND;
  const int tid = threadIdx.x;
  const uint32_t sa = (uint32_t)__cvta_generic_to_shared(smh);
  const uint32_t sbm = (uint32_t)__cvta_generic_to_shared(smh + 3 * GK_STAGEW);

  #define GH_ISSUE(kt, st) do { \
    _Pragma("unroll") \
    for (int i = 0; i < 4; i++) { \
      const int id = tid + 256 * i; \
      const int r = id >> 3, c = id & 7; \
      const uint32_t wo = (uint32_t)((st) * GK_STAGEW + r * 36 + c * 4) * 4; \
      cpasync16(sa + wo, A + (size_t)(bm + r) * K + (kt) * 64 + c * 8); \
      cpasync16(sbm + wo, W + (size_t)(bn + r) * K + (kt) * 64 + c * 8); \
    } \
    asm volatile("cp.async.commit_group;" ::); \
  } while (0)

  GH_ISSUE(0, 0);
  GH_ISSUE(1, 1);

  const int niter = K / 64;   // 32
  int st_c = 0, st_p = 2;
  for (int kt = 0; kt < niter; kt++) {
    asm volatile("cp.async.wait_group 1;" ::);
    __syncthreads();
    if (kt + 2 < niter) GH_ISSUE(kt + 2, st_p);
    else asm volatile("cp.async.commit_group;" ::);

    const uint32_t ab = sa + (uint32_t)st_c * GK_STAGEW * 4;
    const uint32_t bb = sbm + (uint32_t)st_c * GK_STAGEW * 4;
    #pragma unroll
    for (int ks = 0; ks < 4; ks++) {
      unsigned afr[4][4], bfr[4][2];
      #pragma unroll
      for (int mi = 0; mi < 4; mi++)
        ldsm4(afr[mi][0], afr[mi][1], afr[mi][2], afr[mi][3],
              ab + aoff[mi] + ks * 32);
      #pragma unroll
      for (int n2 = 0; n2 < 2; n2++)
        ldsm4(bfr[2 * n2][0], bfr[2 * n2][1], bfr[2 * n2 + 1][0],
              bfr[2 * n2 + 1][1], bb + boff[n2] + ks * 32);
      #pragma unroll
      for (int mi = 0; mi < 4; mi++)
        #pragma unroll
        for (int ni = 0; ni < 4; ni++)
          mma_f16(acc[mi][ni], afr[mi][0], afr[mi][1], afr[mi][2], afr[mi][3],
                  bfr[ni][0], bfr[ni][1]);
    }
    st_c = (st_c == 2) ? 0 : st_c + 1;
    st_p = (st_p == 2) ? 0 : st_p + 1;
  }
  #undef GH_ISSUE
}

// Fused QKV GEMM: blockIdx.z selects weight + epilogue.
// z=0: Q -> RoPE scatter (scaled); z=1: K -> RoPE scatter; z=2: V -> transposed.
__global__ void __launch_bounds__(256, 2) gemm_qkv(
    const __half* __restrict__ A,
    const __half* __restrict__ Wq, const __half* __restrict__ Wk,
    const __half* __restrict__ Wv,
    __half* __restrict__ Qo, __half* __restrict__ Ko, __half* __restrict__ Vo,
    const float* __restrict__ fcos, const float* __restrict__ fsin)
{
  extern __shared__ unsigned smh[];
  const int z = blockIdx.z;
  const __half* W = (z == 0) ? Wq : (z == 1) ? Wk : Wv;
  const int bm = blockIdx.y * 128;
  const int bn = blockIdx.x * 128;
  const int tid = threadIdx.x;
  const int warp = tid >> 5, lane = tid & 31;
  const int wm0 = (warp >> 2) * 64;
  const int wn0 = (warp & 3) * 32;
  const int g = lane >> 2, tk = lane & 3;
  const int l8 = lane & 7, lm = lane >> 3;

  uint32_t aoff[4], boff[2];
  #pragma unroll
  for (int mi = 0; mi < 4; mi++)
    aoff[mi] = (uint32_t)(((wm0 + mi * 16 + l8 + (lm & 1) * 8) * 36
                           + (lm >> 1) * 4) * 4);
  #pragma unroll
  for (int n2 = 0; n2 < 2; n2++)
    boff[n2] = (uint32_t)(((wn0 + n2 * 16 + l8 + (lm >> 1) * 8) * 36
                           + (lm & 1) * 4) * 4);

  float acc[4][4][4];
  #pragma unroll
  for (int mi = 0; mi < 4; mi++)
    #pragma unroll
    for (int ni = 0; ni < 4; ni++)
      #pragma unroll
      for (int cc = 0; cc < 4; cc++) acc[mi][ni][cc] = 0.f;

  gemm_mainloop(A, W, bm, bn, smh, acc, aoff, boff);

  const float outscale = (z == 0) ? 0.08838834764831845f : 1.0f;
  __half* Ch = (z == 0) ? Qo : (z == 1) ? Ko : Vo;

  #pragma unroll
  for (int mi = 0; mi < 4; mi++) {
    #pragma unroll
    for (int half = 0; half < 2; half++) {
      const int m = bm + wm0 + mi * 16 + g + half * 8;
      const int b = m / NS, s = m % NS;
      #pragma unroll
      for (int ni = 0; ni < 4; ni++) {
        float v0 = acc[mi][ni][half * 2 + 0];
        float v1 = acc[mi][ni][half * 2 + 1];
        const int n = bn + wn0 + ni * 8 + tk * 2;
        const int h = n / NDH, d = n % NDH;
        if (z == 2) {  // V transposed [b,h,dh,s]
          __half* dst = Ch + (((size_t)(b * NH + h)) * NDH + d) * NS + s;
          dst[0]  = __float2half_rn(v0);
          dst[NS] = __float2half_rn(v1);
        } else {       // Q/K: RoPE + head scatter
          __half* dst = Ch + (((size_t)(b * NH + h)) * NS + s) * NDH;
          const int pi = d >> 1;
          const float cc = fcos[s * (NDH / 2) + pi];
          const float sn = fsin[s * (NDH / 2) + pi];
          v0 *= outscale; v1 *= outscale;
          __half2 vv = __floats2half2_rn(v0 * cc - v1 * sn, v0 * sn + v1 * cc);
          *(__half2*)&dst[d] = vv;
        }
      }
    }
  }
}

// Output GEMM (MODE 0: fp32 row-major store), same core.
__global__ void __launch_bounds__(256, 2) gemm_out(
    const __half* __restrict__ A, const __half* __restrict__ W,
    float* __restrict__ C)
{
  extern __shared__ unsigned smh[];
  const int bm = blockIdx.y * 128;
  const int bn = blockIdx.x * 128;
  const int tid = threadIdx.x;
  const int warp = tid >> 5, lane = tid & 31;
  const int wm0 = (warp >> 2) * 64;
  const int wn0 = (warp & 3) * 32;
  const int g = lane >> 2, tk = lane & 3;
  const int l8 = lane & 7, lm = lane >> 3;

  uint32_t aoff[4], boff[2];
  #pragma unroll
  for (int mi = 0; mi < 4; mi++)
    aoff[mi] = (uint32_t)(((wm0 + mi * 16 + l8 + (lm & 1) * 8) * 36
                           + (lm >> 1) * 4) * 4);
  #pragma unroll
  for (int n2 = 0; n2 < 2; n2++)
    boff[n2] = (uint32_t)(((wn0 + n2 * 16 + l8 + (lm >> 1) * 8) * 36
                           + (lm & 1) * 4) * 4);

  float acc[4][4][4];
  #pragma unroll
  for (int mi = 0; mi < 4; mi++)
    #pragma unroll
    for (int ni = 0; ni < 4; ni++)
      #pragma unroll
      for (int cc = 0; cc < 4; cc++) acc[mi][ni][cc] = 0.f;

  gemm_mainloop(A, W, bm, bn, smh, acc, aoff, boff);

  #pragma unroll
  for (int mi = 0; mi < 4; mi++) {
    #pragma unroll
    for (int half = 0; half < 2; half++) {
      const int m = bm + wm0 + mi * 16 + g + half * 8;
      #pragma unroll
      for (int ni = 0; ni < 4; ni++) {
        const int n = bn + wn0 + ni * 8 + tk * 2;
        float2 vv = {acc[mi][ni][half * 2 + 0], acc[mi][ni][half * 2 + 1]};
        *(float2*)&C[(size_t)m * ND + n] = vv;
      }
    }
  }
}

// ============================================================================
// Flash attention (causal), fp16 mma + ldmatrix, cp.async 3-stage K/V ring.
// Br=128 (8 warps x 16 rows), Bc=64. (unchanged from R12)
// ============================================================================
#define FL_QPITCH 68
#define FL_VPITCH 36
#define FL_KWORDS (64 * FL_QPITCH)                 // 4352
#define FL_VWORDS (128 * FL_VPITCH)                // 4608
#define FL_STAGEW (FL_KWORDS + FL_VWORDS)          // 8960
#define FL_SMEM ((128 * FL_QPITCH + 3 * FL_STAGEW) * 4)

__global__ void __launch_bounds__(256) flash_tc(
    const __half* __restrict__ gq, const __half* __restrict__ gk,
    const __half* __restrict__ gvt, __half* __restrict__ ctx)
{
  extern __shared__ unsigned smf[];
  unsigned* Qs = smf;
  unsigned* St = smf + 128 * FL_QPITCH;   // 3 stages

  const int bh = blockIdx.y;
  const int b = bh >> 4, h = bh & 15;
  const int qb = blockIdx.x * 128;
  const int tid = threadIdx.x;
  const int warp = tid >> 5, lane = tid & 31;
  const int g = lane >> 2, tk = lane & 3;
  const int l8 = lane & 7, lm = lane >> 3;
  const int m0 = warp * 16;
  const int qrow_max = qb + m0 + 15;

  const __half* kbase = gk + (size_t)bh * NS * NDH;
  const __half* vtb = gvt + (size_t)bh * NDH * NS;
  const int ntiles = qb / 64 + 2;
  const uint32_t sQs = (uint32_t)__cvta_generic_to_shared(Qs);
  const uint32_t sSt = (uint32_t)__cvta_generic_to_shared(St);

  const uint32_t qoff = sQs +
    (uint32_t)(((m0 + l8 + (lm & 1) * 8) * FL_QPITCH + (lm >> 1) * 4) * 4);
  uint32_t koff[4];
  #pragma unroll
  for (int n2 = 0; n2 < 4; n2++)
    koff[n2] = (uint32_t)(((n2 * 16 + l8 + (lm >> 1) * 8) * FL_QPITCH
                           + (lm & 1) * 4) * 4);
  uint32_t voff[8];
  #pragma unroll
  for (int mi = 0; mi < 8; mi++)
    voff[mi] = (uint32_t)((FL_KWORDS + (mi * 16 + l8 + (lm & 1) * 8) * FL_VPITCH
                           + (lm >> 1) * 4) * 4);

  #define FL_ISSUE(t, s) do { \
    if ((t) < ntiles) { \
      const int k0i = (t) * 64; \
      const uint32_t kd = sSt + (uint32_t)(s) * FL_STAGEW * 4; \
      const uint32_t vd = kd + FL_KWORDS * 4; \
      _Pragma("unroll") \
      for (int i = 0; i < 4; i++) { \
        const int id = tid + 256 * i; \
        const int kr = id >> 4, kc = id & 15; \
        cpasync16(kd + (uint32_t)(kr * FL_QPITCH + kc * 4) * 4, \
                  kbase + (size_t)(k0i + kr) * NDH + kc * 8); \
        const int vr = id >> 3, vc = id & 7; \
        cpasync16(vd + (uint32_t)(vr * FL_VPITCH + vc * 4) * 4, \
                  vtb + (size_t)vr * NS + k0i + vc * 8); \
      } \
    } \
    asm volatile("cp.async.commit_group;" ::); \
  } while (0)

  FL_ISSUE(0, 0);
  FL_ISSUE(1, 1);

  const __half* qbase = gq + ((size_t)bh * NS + qb) * NDH;
  #pragma unroll
  for (int i = 0; i < 8; i++) {
    int idx = i * 256 + tid;
    int row = idx >> 4, c = idx & 15;
    uint4 v = *(const uint4*)(qbase + (size_t)row * NDH + c * 8);
    *(uint4*)(Qs + row * FL_QPITCH + c * 4) = v;
  }

  float oacc[8][2][4];
  #pragma unroll
  for (int mi = 0; mi < 8; mi++)
    #pragma unroll
    for (int nt = 0; nt < 2; nt++)
      #pragma unroll
      for (int c = 0; c < 4; c++) oacc[mi][nt][c] = 0.f;
  float mrow0 = -1e30f, mrow1 = -1e30f, lrow0 = 0.f, lrow1 = 0.f;

  for (int t = 0; t < ntiles; t++) {
    const int k0 = t * 64;
    const int s = t % 3;
    asm volatile("cp.async.wait_group 1;" ::);
    __syncthreads();
    FL_ISSUE(t + 2, (t + 2) % 3);
    if (k0 > qrow_max) continue;

    const uint32_t stb = sSt + (uint32_t)s * FL_STAGEW * 4;

    float sacc[8][4];
    #pragma unroll
    for (int nt = 0; nt < 8; nt++)
      #pragma unroll
      for (int c = 0; c < 4; c++) sacc[nt][c] = 0.f;

    #pragma unroll
    for (int ks = 0; ks < 8; ks++) {
      unsigned a0, a1, a2, a3;
      ldsm4(a0, a1, a2, a3, qoff + ks * 32);
      unsigned kf[8][2];
      #pragma unroll
      for (int n2 = 0; n2 < 4; n2++)
        ldsm4(kf[2 * n2][0], kf[2 * n2][1], kf[2 * n2 + 1][0],
              kf[2 * n2 + 1][1], stb + koff[n2] + ks * 32);
      #pragma unroll
      for (int nt = 0; nt < 8; nt++)
        mma_f16(sacc[nt], a0, a1, a2, a3, kf[nt][0], kf[nt][1]);
    }

    if (k0 + 63 > qb + m0) {
      const int r0q = qb + m0 + g, r1q = r0q + 8;
      #pragma unroll
      for (int nt = 0; nt < 8; nt++) {
        const int key0 = k0 + nt * 8 + 2 * tk;
        if (key0     > r0q) sacc[nt][0] = -1e30f;
        if (key0 + 1 > r0q) sacc[nt][1] = -1e30f;
        if (key0     > r1q) sacc[nt][2] = -1e30f;
        if (key0 + 1 > r1q) sacc[nt][3] = -1e30f;
      }
    }

    float mx0 = mrow0, mx1 = mrow1;
    #pragma unroll
    for (int nt = 0; nt < 8; nt++) {
      mx0 = fmaxf(mx0, fmaxf(sacc[nt][0], sacc[nt][1]));
      mx1 = fmaxf(mx1, fmaxf(sacc[nt][2], sacc[nt][3]));
    }
    mx0 = fmaxf(mx0, __shfl_xor_sync(0xffffffffu, mx0, 1));
    mx0 = fmaxf(mx0, __shfl_xor_sync(0xffffffffu, mx0, 2));
    mx1 = fmaxf(mx1, __shfl_xor_sync(0xffffffffu, mx1, 1));
    mx1 = fmaxf(mx1, __shfl_xor_sync(0xffffffffu, mx1, 2));
    const float al0 = __expf(mrow0 - mx0);
    const float al1 = __expf(mrow1 - mx1);
    mrow0 = mx0; mrow1 = mx1;
    lrow0 *= al0; lrow1 *= al1;

    const float af00 = __shfl_sync(0xffffffffu, al0, 8 * tk);
    const float af01 = __shfl_sync(0xffffffffu, al0, 8 * tk + 4);
    const float af10 = __shfl_sync(0xffffffffu, al1, 8 * tk);
    const float af11 = __shfl_sync(0xffffffffu, al1, 8 * tk + 4);
    #pragma unroll
    for (int mi = 0; mi < 8; mi++) {
      oacc[mi][0][0] *= af00; oacc[mi][0][1] *= af01;
      oacc[mi][0][2] *= af00; oacc[mi][0][3] *= af01;
      oacc[mi][1][0] *= af10; oacc[mi][1][1] *= af11;
      oacc[mi][1][2] *= af10; oacc[mi][1][3] *= af11;
    }

    float cb0 = 0.f, cb1 = 0.f;
    #pragma unroll
    for (int nt = 0; nt < 8; nt++) {
      sacc[nt][0] = __expf(sacc[nt][0] - mx0);
      sacc[nt][1] = __expf(sacc[nt][1] - mx0);
      sacc[nt][2] = __expf(sacc[nt][2] - mx1);
      sacc[nt][3] = __expf(sacc[nt][3] - mx1);
      cb0 += sacc[nt][0] + sacc[nt][1];
      cb1 += sacc[nt][2] + sacc[nt][3];
    }
    cb0 += __shfl_xor_sync(0xffffffffu, cb0, 1);
    cb0 += __shfl_xor_sync(0xffffffffu, cb0, 2);
    cb1 += __shfl_xor_sync(0xffffffffu, cb1, 1);
    cb1 += __shfl_xor_sync(0xffffffffu, cb1, 2);
    lrow0 += cb0; lrow1 += cb1;

    #pragma unroll
    for (int ks = 0; ks < 4; ks++) {
      const unsigned bl0 = packh2(sacc[2 * ks][0],     sacc[2 * ks][1]);
      const unsigned bl1 = packh2(sacc[2 * ks + 1][0], sacc[2 * ks + 1][1]);
      const unsigned bh0 = packh2(sacc[2 * ks][2],     sacc[2 * ks][3]);
      const unsigned bh1 = packh2(sacc[2 * ks + 1][2], sacc[2 * ks + 1][3]);
      #pragma unroll
      for (int mi = 0; mi < 8; mi++) {
        unsigned va0, va1, va2, va3;
        ldsm4(va0, va1, va2, va3, stb + voff[mi] + ks * 32);
        mma_f16(oacc[mi][0], va0, va1, va2, va3, bl0, bl1);
        mma_f16(oacc[mi][1], va0, va1, va2, va3, bh0, bh1);
      }
    }
  }

  const float l00 = __shfl_sync(0xffffffffu, lrow0, 8 * tk);
  const float l01 = __shfl_sync(0xffffffffu, lrow0, 8 * tk + 4);
  const float l10 = __shfl_sync(0xffffffffu, lrow1, 8 * tk);
  const float l11 = __shfl_sync(0xffffffffu, lrow1, 8 * tk + 4);
  const float i00 = 1.f / l00, i01 = 1.f / l01;
  const float i10 = 1.f / l10, i11 = 1.f / l11;

  __half* cp = ctx + ((size_t)(b * NS + qb + m0)) * ND + h * NDH;
  #pragma unroll
  for (int mi = 0; mi < 8; mi++) {
    const int d0 = mi * 16 + g;
    cp[(size_t)(2 * tk) * ND + d0]         = __float2half_rn(oacc[mi][0][0] * i00);
    cp[(size_t)(2 * tk + 1) * ND + d0]     = __float2half_rn(oacc[mi][0][1] * i01);
    cp[(size_t)(2 * tk) * ND + d0 + 8]     = __float2half_rn(oacc[mi][0][2] * i00);
    cp[(size_t)(2 * tk + 1) * ND + d0 + 8] = __float2half_rn(oacc[mi][0][3] * i01);
    cp[(size_t)(8 + 2 * tk) * ND + d0]     = __float2half_rn(oacc[mi][1][0] * i10);
    cp[(size_t)(9 + 2 * tk) * ND + d0]     = __float2half_rn(oacc[mi][1][1] * i11);
    cp[(size_t)(8 + 2 * tk) * ND + d0 + 8] = __float2half_rn(oacc[mi][1][2] * i10);
    cp[(size_t)(9 + 2 * tk) * ND + d0 + 8] = __float2half_rn(oacc[mi][1][3] * i11);
  }
}

extern "C" void kernel_launch(void* const* d_in, const int* in_sizes, int n_in,
                              void* d_out, int out_size) {
  const float* x  = (const float*)d_in[0];
  const float* fc = (const float*)d_in[1];
  const float* fs = (const float*)d_in[2];
  // d_in[3] is the mask; causal handled analytically
  const float* wq = (const float*)d_in[4];
  const float* wk = (const float*)d_in[5];
  const float* wv = (const float*)d_in[6];
  const float* wo = (const float*)d_in[7];

  __half *qh, *kh, *vt, *ctx, *xh, *wqh, *wkh, *wvh, *woh;
  cudaGetSymbolAddress((void**)&qh,  g_qh);
  cudaGetSymbolAddress((void**)&kh,  g_kh);
  cudaGetSymbolAddress((void**)&vt,  g_vt);
  cudaGetSymbolAddress((void**)&ctx, g_ctx);
  cudaGetSymbolAddress((void**)&xh,  g_xh);
  cudaGetSymbolAddress((void**)&wqh, g_wqh);
  cudaGetSymbolAddress((void**)&wkh, g_wkh);
  cudaGetSymbolAddress((void**)&wvh, g_wvh);
  cudaGetSymbolAddress((void**)&woh, g_woh);

  cudaFuncSetAttribute(flash_tc, cudaFuncAttributeMaxDynamicSharedMemorySize, FL_SMEM);
  cudaFuncSetAttribute(gemm_qkv, cudaFuncAttributeMaxDynamicSharedMemorySize, GH_SMEM);
  cudaFuncSetAttribute(gemm_out, cudaFuncAttributeMaxDynamicSharedMemorySize, GH_SMEM);

  // Prep: convert x + all 4 weights to fp16 (2 launches).
  const int nx4 = NM * ND / 4;
  tohalf_k<<<nx4 / 256, 256>>>(x, xh, nx4);
  tohalf4_k<<<4 * (ND * ND / 4) / 256, 256>>>(wq, wk, wv, wo, wqh, wkh, wvh, woh);

  // Fused QKV GEMM: one launch, z = 0/1/2.
  dim3 gq3(ND / 128, NM / 128, 3);
  gemm_qkv<<<gq3, 256, GH_SMEM>>>(xh, wqh, wkh, wvh, qh, kh, vt, fc, fs);

  dim3 fg(NS / 128, NB * NH);
  flash_tc<<<fg, 256, FL_SMEM>>>(qh, kh, vt, ctx);

  dim3 gg(ND / 128, NM / 128);
  gemm_out<<<gg, 256, GH_SMEM>>>(ctx, woh, (float*)d_out);
}

// round 14
// speedup vs baseline: 1.2623x; 1.0209x over previous
#include <cuda_runtime.h>
#include <cuda_fp16.h>
#include <stdint.h>
#include <math.h>

#define NB 2
#define NS 2048
#define ND 2048
#define NH 16
#define NDH 128
#define NM (NB*NS)

// Scratch (device globals; no allocation allowed)
__device__ __half g_qh[(size_t)NB*NH*NS*NDH];
__device__ __half g_kh[(size_t)NB*NH*NS*NDH];
__device__ __half g_vt[(size_t)NB*NH*NDH*NS];   // V transposed: [b,h,dh,s] fp16
__device__ __half g_ctx[(size_t)NB*NS*ND];      // attention output, fp16
__device__ __half g_xh[(size_t)NM*ND];          // x in fp16
__device__ __half g_wqh[(size_t)ND*ND];
__device__ __half g_wkh[(size_t)ND*ND];
__device__ __half g_wvh[(size_t)ND*ND];
__device__ __half g_woh[(size_t)ND*ND];

__device__ __forceinline__ unsigned packh2(float lo, float hi) {
  __half2 h = __floats2half2_rn(lo, hi);
  return *(unsigned*)&h;
}
__device__ __forceinline__ void mma_f16(float* c, unsigned a0, unsigned a1,
                                        unsigned a2, unsigned a3,
                                        unsigned b0, unsigned b1) {
  asm volatile(
    "mma.sync.aligned.m16n8k16.row.col.f32.f16.f16.f32 "
    "{%0,%1,%2,%3},{%4,%5,%6,%7},{%8,%9},{%0,%1,%2,%3};\n"
    : "+f"(c[0]), "+f"(c[1]), "+f"(c[2]), "+f"(c[3])
    : "r"(a0), "r"(a1), "r"(a2), "r"(a3), "r"(b0), "r"(b1));
}
__device__ __forceinline__ void ldsm4(unsigned& r0, unsigned& r1,
                                      unsigned& r2, unsigned& r3,
                                      uint32_t addr) {
  asm volatile(
    "ldmatrix.sync.aligned.m8n8.x4.shared.b16 {%0,%1,%2,%3}, [%4];"
    : "=r"(r0), "=r"(r1), "=r"(r2), "=r"(r3) : "r"(addr));
}
__device__ __forceinline__ void cpasync16(uint32_t dst, const void* src) {
  asm volatile("cp.async.cg.shared.global [%0], [%1], 16;" :: "r"(dst),
               "l"(src));
}

// fp32 -> fp16 conversion, vectorized.
__global__ void tohalf_k(const float* __restrict__ src,
                         __half* __restrict__ dst, int n4) {
  int i = blockIdx.x * 256 + threadIdx.x;
  if (i < n4) {
    float4 v = ((const float4*)src)[i];
    __half2 h0 = __floats2half2_rn(v.x, v.y);
    __half2 h1 = __floats2half2_rn(v.z, v.w);
    uint2 u = {*(unsigned*)&h0, *(unsigned*)&h1};
    ((uint2*)dst)[i] = u;
  }
}

// 4 weight matrices (ND*ND each) in one launch.
__global__ void tohalf4_k(const float* __restrict__ s0, const float* __restrict__ s1,
                          const float* __restrict__ s2, const float* __restrict__ s3,
                          __half* __restrict__ d0, __half* __restrict__ d1,
                          __half* __restrict__ d2, __half* __restrict__ d3) {
  const int per = (ND * ND / 4) / 256;       // blocks per tensor
  const int which = blockIdx.x / per;
  const int i = (blockIdx.x % per) * 256 + threadIdx.x;
  const float* src = (which == 0) ? s0 : (which == 1) ? s1 : (which == 2) ? s2 : s3;
  __half* dst = (which == 0) ? d0 : (which == 1) ? d1 : (which == 2) ? d2 : d3;
  float4 v = ((const float4*)src)[i];
  __half2 h0 = __floats2half2_rn(v.x, v.y);
  __half2 h1 = __floats2half2_rn(v.z, v.w);
  uint2 u = {*(unsigned*)&h0, *(unsigned*)&h1};
  ((uint2*)dst)[i] = u;
}

// ============================================================================
// GEMM core (R12): fp16 mma.sync + ldmatrix, cp.async 3-stage, 128x128,
// K-tile 64, warp tile 64x32, 2 CTA/SM, one __syncthreads per K-tile.
// ============================================================================
#define GK_STAGEW 4608                 // 128 rows * 36 words
#define GH_SMEM (3 * 2 * GK_STAGEW * 4)

__device__ __forceinline__ void gemm_mainloop(
    const __half* __restrict__ A, const __half* __restrict__ W,
    int bm, int bn, unsigned* smh, float acc[4][4][4],
    uint32_t* aoff, uint32_t* boff)
{
  const int K = ND;
  const int tid = threadIdx.x;
  const uint32_t sa = (uint32_t)__cvta_generic_to_shared(smh);
  const uint32_t sbm = (uint32_t)__cvta_generic_to_shared(smh + 3 * GK_STAGEW);

  #define GH_ISSUE(kt, st) do { \
    _Pragma("unroll") \
    for (int i = 0; i < 4; i++) { \
      const int id = tid + 256 * i; \
      const int r = id >> 3, c = id & 7; \
      const uint32_t wo = (uint32_t)((st) * GK_STAGEW + r * 36 + c * 4) * 4; \
      cpasync16(sa + wo, A + (size_t)(bm + r) * K + (kt) * 64 + c * 8); \
      cpasync16(sbm + wo, W + (size_t)(bn + r) * K + (kt) * 64 + c * 8); \
    } \
    asm volatile("cp.async.commit_group;" ::); \
  } while (0)

  GH_ISSUE(0, 0);
  GH_ISSUE(1, 1);

  const int niter = K / 64;   // 32
  int st_c = 0, st_p = 2;
  for (int kt = 0; kt < niter; kt++) {
    asm volatile("cp.async.wait_group 1;" ::);
    __syncthreads();
    if (kt + 2 < niter) GH_ISSUE(kt + 2, st_p);
    else asm volatile("cp.async.commit_group;" ::);

    const uint32_t ab = sa + (uint32_t)st_c * GK_STAGEW * 4;
    const uint32_t bb = sbm + (uint32_t)st_c * GK_STAGEW * 4;
    #pragma unroll
    for (int ks = 0; ks < 4; ks++) {
      unsigned afr[4][4], bfr[4][2];
      #pragma unroll
      for (int mi = 0; mi < 4; mi++)
        ldsm4(afr[mi][0], afr[mi][1], afr[mi][2], afr[mi][3],
              ab + aoff[mi] + ks * 32);
      #pragma unroll
      for (int n2 = 0; n2 < 2; n2++)
        ldsm4(bfr[2 * n2][0], bfr[2 * n2][1], bfr[2 * n2 + 1][0],
              bfr[2 * n2 + 1][1], bb + boff[n2] + ks * 32);
      #pragma unroll
      for (int mi = 0; mi < 4; mi++)
        #pragma unroll
        for (int ni = 0; ni < 4; ni++)
          mma_f16(acc[mi][ni], afr[mi][0], afr[mi][1], afr[mi][2], afr[mi][3],
                  bfr[ni][0], bfr[ni][1]);
    }
    st_c = (st_c == 2) ? 0 : st_c + 1;
    st_p = (st_p == 2) ? 0 : st_p + 1;
  }
  #undef GH_ISSUE
}

// Fused QKV GEMM: blockIdx.z selects weight + epilogue.
__global__ void __launch_bounds__(256, 2) gemm_qkv(
    const __half* __restrict__ A,
    const __half* __restrict__ Wq, const __half* __restrict__ Wk,
    const __half* __restrict__ Wv,
    __half* __restrict__ Qo, __half* __restrict__ Ko, __half* __restrict__ Vo,
    const float* __restrict__ fcos, const float* __restrict__ fsin)
{
  extern __shared__ unsigned smh[];
  const int z = blockIdx.z;
  const __half* W = (z == 0) ? Wq : (z == 1) ? Wk : Wv;
  const int bm = blockIdx.y * 128;
  const int bn = blockIdx.x * 128;
  const int tid = threadIdx.x;
  const int warp = tid >> 5, lane = tid & 31;
  const int wm0 = (warp >> 2) * 64;
  const int wn0 = (warp & 3) * 32;
  const int g = lane >> 2, tk = lane & 3;
  const int l8 = lane & 7, lm = lane >> 3;

  uint32_t aoff[4], boff[2];
  #pragma unroll
  for (int mi = 0; mi < 4; mi++)
    aoff[mi] = (uint32_t)(((wm0 + mi * 16 + l8 + (lm & 1) * 8) * 36
                           + (lm >> 1) * 4) * 4);
  #pragma unroll
  for (int n2 = 0; n2 < 2; n2++)
    boff[n2] = (uint32_t)(((wn0 + n2 * 16 + l8 + (lm >> 1) * 8) * 36
                           + (lm & 1) * 4) * 4);

  float acc[4][4][4];
  #pragma unroll
  for (int mi = 0; mi < 4; mi++)
    #pragma unroll
    for (int ni = 0; ni < 4; ni++)
      #pragma unroll
      for (int cc = 0; cc < 4; cc++) acc[mi][ni][cc] = 0.f;

  gemm_mainloop(A, W, bm, bn, smh, acc, aoff, boff);

  const float outscale = (z == 0) ? 0.08838834764831845f : 1.0f;
  __half* Ch = (z == 0) ? Qo : (z == 1) ? Ko : Vo;

  #pragma unroll
  for (int mi = 0; mi < 4; mi++) {
    #pragma unroll
    for (int half = 0; half < 2; half++) {
      const int m = bm + wm0 + mi * 16 + g + half * 8;
      const int b = m / NS, s = m % NS;
      #pragma unroll
      for (int ni = 0; ni < 4; ni++) {
        float v0 = acc[mi][ni][half * 2 + 0];
        float v1 = acc[mi][ni][half * 2 + 1];
        const int n = bn + wn0 + ni * 8 + tk * 2;
        const int h = n / NDH, d = n % NDH;
        if (z == 2) {  // V transposed [b,h,dh,s]
          __half* dst = Ch + (((size_t)(b * NH + h)) * NDH + d) * NS + s;
          dst[0]  = __float2half_rn(v0);
          dst[NS] = __float2half_rn(v1);
        } else {       // Q/K: RoPE + head scatter
          __half* dst = Ch + (((size_t)(b * NH + h)) * NS + s) * NDH;
          const int pi = d >> 1;
          const float cc = fcos[s * (NDH / 2) + pi];
          const float sn = fsin[s * (NDH / 2) + pi];
          v0 *= outscale; v1 *= outscale;
          __half2 vv = __floats2half2_rn(v0 * cc - v1 * sn, v0 * sn + v1 * cc);
          *(__half2*)&dst[d] = vv;
        }
      }
    }
  }
}

// Output GEMM (fp32 row-major store), same core.
__global__ void __launch_bounds__(256, 2) gemm_out(
    const __half* __restrict__ A, const __half* __restrict__ W,
    float* __restrict__ C)
{
  extern __shared__ unsigned smh[];
  const int bm = blockIdx.y * 128;
  const int bn = blockIdx.x * 128;
  const int tid = threadIdx.x;
  const int warp = tid >> 5, lane = tid & 31;
  const int wm0 = (warp >> 2) * 64;
  const int wn0 = (warp & 3) * 32;
  const int g = lane >> 2, tk = lane & 3;
  const int l8 = lane & 7, lm = lane >> 3;

  uint32_t aoff[4], boff[2];
  #pragma unroll
  for (int mi = 0; mi < 4; mi++)
    aoff[mi] = (uint32_t)(((wm0 + mi * 16 + l8 + (lm & 1) * 8) * 36
                           + (lm >> 1) * 4) * 4);
  #pragma unroll
  for (int n2 = 0; n2 < 2; n2++)
    boff[n2] = (uint32_t)(((wn0 + n2 * 16 + l8 + (lm >> 1) * 8) * 36
                           + (lm & 1) * 4) * 4);

  float acc[4][4][4];
  #pragma unroll
  for (int mi = 0; mi < 4; mi++)
    #pragma unroll
    for (int ni = 0; ni < 4; ni++)
      #pragma unroll
      for (int cc = 0; cc < 4; cc++) acc[mi][ni][cc] = 0.f;

  gemm_mainloop(A, W, bm, bn, smh, acc, aoff, boff);

  #pragma unroll
  for (int mi = 0; mi < 4; mi++) {
    #pragma unroll
    for (int half = 0; half < 2; half++) {
      const int m = bm + wm0 + mi * 16 + g + half * 8;
      #pragma unroll
      for (int ni = 0; ni < 4; ni++) {
        const int n = bn + wn0 + ni * 8 + tk * 2;
        float2 vv = {acc[mi][ni][half * 2 + 0], acc[mi][ni][half * 2 + 1]};
        *(float2*)&C[(size_t)m * ND + n] = vv;
      }
    }
  }
}

// ============================================================================
// Flash attention (causal), fp16 mma + ldmatrix.
// NOW: 2-stage K/V ring (104 KB smem -> 2 CTA/SM), two syncs per tile.
// Br=128 (8 warps x 16 rows), Bc=64.
// ============================================================================
#define FL_QPITCH 68
#define FL_VPITCH 36
#define FL_KWORDS (64 * FL_QPITCH)                 // 4352
#define FL_VWORDS (128 * FL_VPITCH)                // 4608
#define FL_STAGEW (FL_KWORDS + FL_VWORDS)          // 8960
#define FL_SMEM ((128 * FL_QPITCH + 2 * FL_STAGEW) * 4)

__global__ void __launch_bounds__(256, 2) flash_tc(
    const __half* __restrict__ gq, const __half* __restrict__ gk,
    const __half* __restrict__ gvt, __half* __restrict__ ctx)
{
  extern __shared__ unsigned smf[];
  unsigned* Qs = smf;
  unsigned* St = smf + 128 * FL_QPITCH;   // 2 stages

  const int bh = blockIdx.y;
  const int b = bh >> 4, h = bh & 15;
  const int qb = blockIdx.x * 128;
  const int tid = threadIdx.x;
  const int warp = tid >> 5, lane = tid & 31;
  const int g = lane >> 2, tk = lane & 3;
  const int l8 = lane & 7, lm = lane >> 3;
  const int m0 = warp * 16;
  const int qrow_max = qb + m0 + 15;

  const __half* kbase = gk + (size_t)bh * NS * NDH;
  const __half* vtb = gvt + (size_t)bh * NDH * NS;
  const int ntiles = qb / 64 + 2;
  const uint32_t sQs = (uint32_t)__cvta_generic_to_shared(Qs);
  const uint32_t sSt = (uint32_t)__cvta_generic_to_shared(St);

  const uint32_t qoff = sQs +
    (uint32_t)(((m0 + l8 + (lm & 1) * 8) * FL_QPITCH + (lm >> 1) * 4) * 4);
  uint32_t koff[4];
  #pragma unroll
  for (int n2 = 0; n2 < 4; n2++)
    koff[n2] = (uint32_t)(((n2 * 16 + l8 + (lm >> 1) * 8) * FL_QPITCH
                           + (lm & 1) * 4) * 4);
  uint32_t voff[8];
  #pragma unroll
  for (int mi = 0; mi < 8; mi++)
    voff[mi] = (uint32_t)((FL_KWORDS + (mi * 16 + l8 + (lm & 1) * 8) * FL_VPITCH
                           + (lm >> 1) * 4) * 4);

  #define FL_ISSUE(t, s) do { \
    if ((t) < ntiles) { \
      const int k0i = (t) * 64; \
      const uint32_t kd = sSt + (uint32_t)(s) * FL_STAGEW * 4; \
      const uint32_t vd = kd + FL_KWORDS * 4; \
      _Pragma("unroll") \
      for (int i = 0; i < 4; i++) { \
        const int id = tid + 256 * i; \
        const int kr = id >> 4, kc = id & 15; \
        cpasync16(kd + (uint32_t)(kr * FL_QPITCH + kc * 4) * 4, \
                  kbase + (size_t)(k0i + kr) * NDH + kc * 8); \
        const int vr = id >> 3, vc = id & 7; \
        cpasync16(vd + (uint32_t)(vr * FL_VPITCH + vc * 4) * 4, \
                  vtb + (size_t)vr * NS + k0i + vc * 8); \
      } \
    } \
    asm volatile("cp.async.commit_group;" ::); \
  } while (0)

  FL_ISSUE(0, 0);
  FL_ISSUE(1, 1);

  const __half* qbase = gq + ((size_t)bh * NS + qb) * NDH;
  #pragma unroll
  for (int i = 0; i < 8; i++) {
    int idx = i * 256 + tid;
    int row = idx >> 4, c = idx & 15;
    uint4 v = *(const uint4*)(qbase + (size_t)row * NDH + c * 8);
    *(uint4*)(Qs + row * FL_QPITCH + c * 4) = v;
  }

  float oacc[8][2][4];
  #pragma unroll
  for (int mi = 0; mi < 8; mi++)
    #pragma unroll
    for (int nt = 0; nt < 2; nt++)
      #pragma unroll
      for (int c = 0; c < 4; c++) oacc[mi][nt][c] = 0.f;
  float mrow0 = -1e30f, mrow1 = -1e30f, lrow0 = 0.f, lrow1 = 0.f;

  for (int t = 0; t < ntiles; t++) {
    const int k0 = t * 64;
    const int s = t & 1;
    // groups issued so far: 0..t+1; wait_group 1 -> tile t landed
    asm volatile("cp.async.wait_group 1;" ::);
    __syncthreads();

    if (k0 <= qrow_max) {
      const uint32_t stb = sSt + (uint32_t)s * FL_STAGEW * 4;

      float sacc[8][4];
      #pragma unroll
      for (int nt = 0; nt < 8; nt++)
        #pragma unroll
        for (int c = 0; c < 4; c++) sacc[nt][c] = 0.f;

      #pragma unroll
      for (int ks = 0; ks < 8; ks++) {
        unsigned a0, a1, a2, a3;
        ldsm4(a0, a1, a2, a3, qoff + ks * 32);
        unsigned kf[8][2];
        #pragma unroll
        for (int n2 = 0; n2 < 4; n2++)
          ldsm4(kf[2 * n2][0], kf[2 * n2][1], kf[2 * n2 + 1][0],
                kf[2 * n2 + 1][1], stb + koff[n2] + ks * 32);
        #pragma unroll
        for (int nt = 0; nt < 8; nt++)
          mma_f16(sacc[nt], a0, a1, a2, a3, kf[nt][0], kf[nt][1]);
      }

      if (k0 + 63 > qb + m0) {
        const int r0q = qb + m0 + g, r1q = r0q + 8;
        #pragma unroll
        for (int nt = 0; nt < 8; nt++) {
          const int key0 = k0 + nt * 8 + 2 * tk;
          if (key0     > r0q) sacc[nt][0] = -1e30f;
          if (key0 + 1 > r0q) sacc[nt][1] = -1e30f;
          if (key0     > r1q) sacc[nt][2] = -1e30f;
          if (key0 + 1 > r1q) sacc[nt][3] = -1e30f;
        }
      }

      float mx0 = mrow0, mx1 = mrow1;
      #pragma unroll
      for (int nt = 0; nt < 8; nt++) {
        mx0 = fmaxf(mx0, fmaxf(sacc[nt][0], sacc[nt][1]));
        mx1 = fmaxf(mx1, fmaxf(sacc[nt][2], sacc[nt][3]));
      }
      mx0 = fmaxf(mx0, __shfl_xor_sync(0xffffffffu, mx0, 1));
      mx0 = fmaxf(mx0, __shfl_xor_sync(0xffffffffu, mx0, 2));
      mx1 = fmaxf(mx1, __shfl_xor_sync(0xffffffffu, mx1, 1));
      mx1 = fmaxf(mx1, __shfl_xor_sync(0xffffffffu, mx1, 2));
      const float al0 = __expf(mrow0 - mx0);
      const float al1 = __expf(mrow1 - mx1);
      mrow0 = mx0; mrow1 = mx1;
      lrow0 *= al0; lrow1 *= al1;

      const float af00 = __shfl_sync(0xffffffffu, al0, 8 * tk);
      const float af01 = __shfl_sync(0xffffffffu, al0, 8 * tk + 4);
      const float af10 = __shfl_sync(0xffffffffu, al1, 8 * tk);
      const float af11 = __shfl_sync(0xffffffffu, al1, 8 * tk + 4);
      #pragma unroll
      for (int mi = 0; mi < 8; mi++) {
        oacc[mi][0][0] *= af00; oacc[mi][0][1] *= af01;
        oacc[mi][0][2] *= af00; oacc[mi][0][3] *= af01;
        oacc[mi][1][0] *= af10; oacc[mi][1][1] *= af11;
        oacc[mi][1][2] *= af10; oacc[mi][1][3] *= af11;
      }

      float cb0 = 0.f, cb1 = 0.f;
      #pragma unroll
      for (int nt = 0; nt < 8; nt++) {
        sacc[nt][0] = __expf(sacc[nt][0] - mx0);
        sacc[nt][1] = __expf(sacc[nt][1] - mx0);
        sacc[nt][2] = __expf(sacc[nt][2] - mx1);
        sacc[nt][3] = __expf(sacc[nt][3] - mx1);
        cb0 += sacc[nt][0] + sacc[nt][1];
        cb1 += sacc[nt][2] + sacc[nt][3];
      }
      cb0 += __shfl_xor_sync(0xffffffffu, cb0, 1);
      cb0 += __shfl_xor_sync(0xffffffffu, cb0, 2);
      cb1 += __shfl_xor_sync(0xffffffffu, cb1, 1);
      cb1 += __shfl_xor_sync(0xffffffffu, cb1, 2);
      lrow0 += cb0; lrow1 += cb1;

      #pragma unroll
      for (int ks = 0; ks < 4; ks++) {
        const unsigned bl0 = packh2(sacc[2 * ks][0],     sacc[2 * ks][1]);
        const unsigned bl1 = packh2(sacc[2 * ks + 1][0], sacc[2 * ks + 1][1]);
        const unsigned bh0 = packh2(sacc[2 * ks][2],     sacc[2 * ks][3]);
        const unsigned bh1 = packh2(sacc[2 * ks + 1][2], sacc[2 * ks + 1][3]);
        #pragma unroll
        for (int mi = 0; mi < 8; mi++) {
          unsigned va0, va1, va2, va3;
          ldsm4(va0, va1, va2, va3, stb + voff[mi] + ks * 32);
          mma_f16(oacc[mi][0], va0, va1, va2, va3, bl0, bl1);
          mma_f16(oacc[mi][1], va0, va1, va2, va3, bh0, bh1);
        }
      }
    }

    __syncthreads();          // all warps done reading stage s
    FL_ISSUE(t + 2, s);       // safe to overwrite stage s
  }

  const float l00 = __shfl_sync(0xffffffffu, lrow0, 8 * tk);
  const float l01 = __shfl_sync(0xffffffffu, lrow0, 8 * tk + 4);
  const float l10 = __shfl_sync(0xffffffffu, lrow1, 8 * tk);
  const float l11 = __shfl_sync(0xffffffffu, lrow1, 8 * tk + 4);
  const float i00 = 1.f / l00, i01 = 1.f / l01;
  const float i10 = 1.f / l10, i11 = 1.f / l11;

  __half* cp = ctx + ((size_t)(b * NS + qb + m0)) * ND + h * NDH;
  #pragma unroll
  for (int mi = 0; mi < 8; mi++) {
    const int d0 = mi * 16 + g;
    cp[(size_t)(2 * tk) * ND + d0]         = __float2half_rn(oacc[mi][0][0] * i00);
    cp[(size_t)(2 * tk + 1) * ND + d0]     = __float2half_rn(oacc[mi][0][1] * i01);
    cp[(size_t)(2 * tk) * ND + d0 + 8]     = __float2half_rn(oacc[mi][0][2] * i00);
    cp[(size_t)(2 * tk + 1) * ND + d0 + 8] = __float2half_rn(oacc[mi][0][3] * i01);
    cp[(size_t)(8 + 2 * tk) * ND + d0]     = __float2half_rn(oacc[mi][1][0] * i10);
    cp[(size_t)(9 + 2 * tk) * ND + d0]     = __float2half_rn(oacc[mi][1][1] * i11);
    cp[(size_t)(8 + 2 * tk) * ND + d0 + 8] = __float2half_rn(oacc[mi][1][2] * i10);
    cp[(size_t)(9 + 2 * tk) * ND + d0 + 8] = __float2half_rn(oacc[mi][1][3] * i11);
  }
}

extern "C" void kernel_launch(void* const* d_in, const int* in_sizes, int n_in,
                              void* d_out, int out_size) {
  const float* x  = (const float*)d_in[0];
  const float* fc = (const float*)d_in[1];
  const float* fs = (const float*)d_in[2];
  // d_in[3] is the mask; causal handled analytically
  const float* wq = (const float*)d_in[4];
  const float* wk = (const float*)d_in[5];
  const float* wv = (const float*)d_in[6];
  const float* wo = (const float*)d_in[7];

  __half *qh, *kh, *vt, *ctx, *xh, *wqh, *wkh, *wvh, *woh;
  cudaGetSymbolAddress((void**)&qh,  g_qh);
  cudaGetSymbolAddress((void**)&kh,  g_kh);
  cudaGetSymbolAddress((void**)&vt,  g_vt);
  cudaGetSymbolAddress((void**)&ctx, g_ctx);
  cudaGetSymbolAddress((void**)&xh,  g_xh);
  cudaGetSymbolAddress((void**)&wqh, g_wqh);
  cudaGetSymbolAddress((void**)&wkh, g_wkh);
  cudaGetSymbolAddress((void**)&wvh, g_wvh);
  cudaGetSymbolAddress((void**)&woh, g_woh);

  cudaFuncSetAttribute(flash_tc, cudaFuncAttributeMaxDynamicSharedMemorySize, FL_SMEM);
  cudaFuncSetAttribute(gemm_qkv, cudaFuncAttributeMaxDynamicSharedMemorySize, GH_SMEM);
  cudaFuncSetAttribute(gemm_out, cudaFuncAttributeMaxDynamicSharedMemorySize, GH_SMEM);

  // Prep: convert x + all 4 weights to fp16 (2 launches).
  const int nx4 = NM * ND / 4;
  tohalf_k<<<nx4 / 256, 256>>>(x, xh, nx4);
  tohalf4_k<<<4 * (ND * ND / 4) / 256, 256>>>(wq, wk, wv, wo, wqh, wkh, wvh, woh);

  // Fused QKV GEMM: one launch, z = 0/1/2.
  dim3 gq3(ND / 128, NM / 128, 3);
  gemm_qkv<<<gq3, 256, GH_SMEM>>>(xh, wqh, wkh, wvh, qh, kh, vt, fc, fs);

  dim3 fg(NS / 128, NB * NH);
  flash_tc<<<fg, 256, FL_SMEM>>>(qh, kh, vt, ctx);

  dim3 gg(ND / 128, NM / 128);
  gemm_out<<<gg, 256, GH_SMEM>>>(ctx, woh, (float*)d_out);
}

// round 15
// speedup vs baseline: 1.3363x; 1.0586x over previous
#include <cuda_runtime.h>
#include <cuda_fp16.h>
#include <stdint.h>
#include <math.h>

#define NB 2
#define NS 2048
#define ND 2048
#define NH 16
#define NDH 128
#define NM (NB*NS)

// Scratch (device globals; no allocation allowed)
__device__ __half g_qh[(size_t)NB*NH*NS*NDH];
__device__ __half g_kh[(size_t)NB*NH*NS*NDH];
__device__ __half g_vt[(size_t)NB*NH*NDH*NS];   // V transposed: [b,h,dh,s] fp16
__device__ __half g_ctx[(size_t)NB*NS*ND];      // attention output, fp16
__device__ __half g_xh[(size_t)NM*ND];          // x in fp16
__device__ __half g_wqh[(size_t)ND*ND];
__device__ __half g_wkh[(size_t)ND*ND];
__device__ __half g_wvh[(size_t)ND*ND];
__device__ __half g_woh[(size_t)ND*ND];

__device__ __forceinline__ unsigned packh2(float lo, float hi) {
  __half2 h = __floats2half2_rn(lo, hi);
  return *(unsigned*)&h;
}
__device__ __forceinline__ void mma_f16(float* c, unsigned a0, unsigned a1,
                                        unsigned a2, unsigned a3,
                                        unsigned b0, unsigned b1) {
  asm volatile(
    "mma.sync.aligned.m16n8k16.row.col.f32.f16.f16.f32 "
    "{%0,%1,%2,%3},{%4,%5,%6,%7},{%8,%9},{%0,%1,%2,%3};\n"
    : "+f"(c[0]), "+f"(c[1]), "+f"(c[2]), "+f"(c[3])
    : "r"(a0), "r"(a1), "r"(a2), "r"(a3), "r"(b0), "r"(b1));
}
__device__ __forceinline__ void ldsm4(unsigned& r0, unsigned& r1,
                                      unsigned& r2, unsigned& r3,
                                      uint32_t addr) {
  asm volatile(
    "ldmatrix.sync.aligned.m8n8.x4.shared.b16 {%0,%1,%2,%3}, [%4];"
    : "=r"(r0), "=r"(r1), "=r"(r2), "=r"(r3) : "r"(addr));
}
__device__ __forceinline__ void cpasync16(uint32_t dst, const void* src) {
  asm volatile("cp.async.cg.shared.global [%0], [%1], 16;" :: "r"(dst),
               "l"(src));
}

// fp32 -> fp16 conversion, vectorized.
__global__ void tohalf_k(const float* __restrict__ src,
                         __half* __restrict__ dst, int n4) {
  int i = blockIdx.x * 256 + threadIdx.x;
  if (i < n4) {
    float4 v = ((const float4*)src)[i];
    __half2 h0 = __floats2half2_rn(v.x, v.y);
    __half2 h1 = __floats2half2_rn(v.z, v.w);
    uint2 u = {*(unsigned*)&h0, *(unsigned*)&h1};
    ((uint2*)dst)[i] = u;
  }
}

// 4 weight matrices (ND*ND each) in one launch.
__global__ void tohalf4_k(const float* __restrict__ s0, const float* __restrict__ s1,
                          const float* __restrict__ s2, const float* __restrict__ s3,
                          __half* __restrict__ d0, __half* __restrict__ d1,
                          __half* __restrict__ d2, __half* __restrict__ d3) {
  const int per = (ND * ND / 4) / 256;       // blocks per tensor
  const int which = blockIdx.x / per;
  const int i = (blockIdx.x % per) * 256 + threadIdx.x;
  const float* src = (which == 0) ? s0 : (which == 1) ? s1 : (which == 2) ? s2 : s3;
  __half* dst = (which == 0) ? d0 : (which == 1) ? d1 : (which == 2) ? d2 : d3;
  float4 v = ((const float4*)src)[i];
  __half2 h0 = __floats2half2_rn(v.x, v.y);
  __half2 h1 = __floats2half2_rn(v.z, v.w);
  uint2 u = {*(unsigned*)&h0, *(unsigned*)&h1};
  ((uint2*)dst)[i] = u;
}

// ============================================================================
// GEMM core (R12): fp16 mma.sync + ldmatrix, cp.async 3-stage, 128x128,
// K-tile 64, warp tile 64x32, 2 CTA/SM, one __syncthreads per K-tile.
// ============================================================================
#define GK_STAGEW 4608                 // 128 rows * 36 words
#define GH_SMEM (3 * 2 * GK_STAGEW * 4)

__device__ __forceinline__ void gemm_mainloop(
    const __half* __restrict__ A, const __half* __restrict__ W,
    int bm, int bn, unsigned* smh, float acc[4][4][4],
    uint32_t* aoff, uint32_t* boff)
{
  const int K = ND;
  const int tid = threadIdx.x;
  const uint32_t sa = (uint32_t)__cvta_generic_to_shared(smh);
  const uint32_t sbm = (uint32_t)__cvta_generic_to_shared(smh + 3 * GK_STAGEW);

  #define GH_ISSUE(kt, st) do { \
    _Pragma("unroll") \
    for (int i = 0; i < 4; i++) { \
      const int id = tid + 256 * i; \
      const int r = id >> 3, c = id & 7; \
      const uint32_t wo = (uint32_t)((st) * GK_STAGEW + r * 36 + c * 4) * 4; \
      cpasync16(sa + wo, A + (size_t)(bm + r) * K + (kt) * 64 + c * 8); \
      cpasync16(sbm + wo, W + (size_t)(bn + r) * K + (kt) * 64 + c * 8); \
    } \
    asm volatile("cp.async.commit_group;" ::); \
  } while (0)

  GH_ISSUE(0, 0);
  GH_ISSUE(1, 1);

  const int niter = K / 64;   // 32
  int st_c = 0, st_p = 2;
  for (int kt = 0; kt < niter; kt++) {
    asm volatile("cp.async.wait_group 1;" ::);
    __syncthreads();
    if (kt + 2 < niter) GH_ISSUE(kt + 2, st_p);
    else asm volatile("cp.async.commit_group;" ::);

    const uint32_t ab = sa + (uint32_t)st_c * GK_STAGEW * 4;
    const uint32_t bb = sbm + (uint32_t)st_c * GK_STAGEW * 4;
    #pragma unroll
    for (int ks = 0; ks < 4; ks++) {
      unsigned afr[4][4], bfr[4][2];
      #pragma unroll
      for (int mi = 0; mi < 4; mi++)
        ldsm4(afr[mi][0], afr[mi][1], afr[mi][2], afr[mi][3],
              ab + aoff[mi] + ks * 32);
      #pragma unroll
      for (int n2 = 0; n2 < 2; n2++)
        ldsm4(bfr[2 * n2][0], bfr[2 * n2][1], bfr[2 * n2 + 1][0],
              bfr[2 * n2 + 1][1], bb + boff[n2] + ks * 32);
      #pragma unroll
      for (int mi = 0; mi < 4; mi++)
        #pragma unroll
        for (int ni = 0; ni < 4; ni++)
          mma_f16(acc[mi][ni], afr[mi][0], afr[mi][1], afr[mi][2], afr[mi][3],
                  bfr[ni][0], bfr[ni][1]);
    }
    st_c = (st_c == 2) ? 0 : st_c + 1;
    st_p = (st_p == 2) ? 0 : st_p + 1;
  }
  #undef GH_ISSUE
}

// Fused QKV GEMM: blockIdx.z selects weight + epilogue.
__global__ void __launch_bounds__(256, 2) gemm_qkv(
    const __half* __restrict__ A,
    const __half* __restrict__ Wq, const __half* __restrict__ Wk,
    const __half* __restrict__ Wv,
    __half* __restrict__ Qo, __half* __restrict__ Ko, __half* __restrict__ Vo,
    const float* __restrict__ fcos, const float* __restrict__ fsin)
{
  extern __shared__ unsigned smh[];
  const int z = blockIdx.z;
  const __half* W = (z == 0) ? Wq : (z == 1) ? Wk : Wv;
  const int bm = blockIdx.y * 128;
  const int bn = blockIdx.x * 128;
  const int tid = threadIdx.x;
  const int warp = tid >> 5, lane = tid & 31;
  const int wm0 = (warp >> 2) * 64;
  const int wn0 = (warp & 3) * 32;
  const int g = lane >> 2, tk = lane & 3;
  const int l8 = lane & 7, lm = lane >> 3;

  uint32_t aoff[4], boff[2];
  #pragma unroll
  for (int mi = 0; mi < 4; mi++)
    aoff[mi] = (uint32_t)(((wm0 + mi * 16 + l8 + (lm & 1) * 8) * 36
                           + (lm >> 1) * 4) * 4);
  #pragma unroll
  for (int n2 = 0; n2 < 2; n2++)
    boff[n2] = (uint32_t)(((wn0 + n2 * 16 + l8 + (lm >> 1) * 8) * 36
                           + (lm & 1) * 4) * 4);

  float acc[4][4][4];
  #pragma unroll
  for (int mi = 0; mi < 4; mi++)
    #pragma unroll
    for (int ni = 0; ni < 4; ni++)
      #pragma unroll
      for (int cc = 0; cc < 4; cc++) acc[mi][ni][cc] = 0.f;

  gemm_mainloop(A, W, bm, bn, smh, acc, aoff, boff);

  const float outscale = (z == 0) ? 0.08838834764831845f : 1.0f;
  __half* Ch = (z == 0) ? Qo : (z == 1) ? Ko : Vo;

  #pragma unroll
  for (int mi = 0; mi < 4; mi++) {
    #pragma unroll
    for (int half = 0; half < 2; half++) {
      const int m = bm + wm0 + mi * 16 + g + half * 8;
      const int b = m / NS, s = m % NS;
      #pragma unroll
      for (int ni = 0; ni < 4; ni++) {
        float v0 = acc[mi][ni][half * 2 + 0];
        float v1 = acc[mi][ni][half * 2 + 1];
        const int n = bn + wn0 + ni * 8 + tk * 2;
        const int h = n / NDH, d = n % NDH;
        if (z == 2) {  // V transposed [b,h,dh,s]
          __half* dst = Ch + (((size_t)(b * NH + h)) * NDH + d) * NS + s;
          dst[0]  = __float2half_rn(v0);
          dst[NS] = __float2half_rn(v1);
        } else {       // Q/K: RoPE + head scatter
          __half* dst = Ch + (((size_t)(b * NH + h)) * NS + s) * NDH;
          const int pi = d >> 1;
          const float cc = fcos[s * (NDH / 2) + pi];
          const float sn = fsin[s * (NDH / 2) + pi];
          v0 *= outscale; v1 *= outscale;
          __half2 vv = __floats2half2_rn(v0 * cc - v1 * sn, v0 * sn + v1 * cc);
          *(__half2*)&dst[d] = vv;
        }
      }
    }
  }
}

// Output GEMM (fp32 row-major store), same core.
__global__ void __launch_bounds__(256, 2) gemm_out(
    const __half* __restrict__ A, const __half* __restrict__ W,
    float* __restrict__ C)
{
  extern __shared__ unsigned smh[];
  const int bm = blockIdx.y * 128;
  const int bn = blockIdx.x * 128;
  const int tid = threadIdx.x;
  const int warp = tid >> 5, lane = tid & 31;
  const int wm0 = (warp >> 2) * 64;
  const int wn0 = (warp & 3) * 32;
  const int g = lane >> 2, tk = lane & 3;
  const int l8 = lane & 7, lm = lane >> 3;

  uint32_t aoff[4], boff[2];
  #pragma unroll
  for (int mi = 0; mi < 4; mi++)
    aoff[mi] = (uint32_t)(((wm0 + mi * 16 + l8 + (lm & 1) * 8) * 36
                           + (lm >> 1) * 4) * 4);
  #pragma unroll
  for (int n2 = 0; n2 < 2; n2++)
    boff[n2] = (uint32_t)(((wn0 + n2 * 16 + l8 + (lm >> 1) * 8) * 36
                           + (lm & 1) * 4) * 4);

  float acc[4][4][4];
  #pragma unroll
  for (int mi = 0; mi < 4; mi++)
    #pragma unroll
    for (int ni = 0; ni < 4; ni++)
      #pragma unroll
      for (int cc = 0; cc < 4; cc++) acc[mi][ni][cc] = 0.f;

  gemm_mainloop(A, W, bm, bn, smh, acc, aoff, boff);

  #pragma unroll
  for (int mi = 0; mi < 4; mi++) {
    #pragma unroll
    for (int half = 0; half < 2; half++) {
      const int m = bm + wm0 + mi * 16 + g + half * 8;
      #pragma unroll
      for (int ni = 0; ni < 4; ni++) {
        const int n = bn + wn0 + ni * 8 + tk * 2;
        float2 vv = {acc[mi][ni][half * 2 + 0], acc[mi][ni][half * 2 + 1]};
        *(float2*)&C[(size_t)m * ND + n] = vv;
      }
    }
  }
}

// ============================================================================
// Flash attention (causal), fp16 mma + ldmatrix, 2-stage K/V ring, 2 CTA/SM.
// CAUSAL LOAD BALANCING: each block processes q-tile bx and q-tile 15-bx
// sequentially (total work identical across blocks); grid 8x32 = 256 blocks
// = exactly one wave at 2 CTA/SM.
// ============================================================================
#define FL_QPITCH 68
#define FL_VPITCH 36
#define FL_KWORDS (64 * FL_QPITCH)                 // 4352
#define FL_VWORDS (128 * FL_VPITCH)                // 4608
#define FL_STAGEW (FL_KWORDS + FL_VWORDS)          // 8960
#define FL_SMEM ((128 * FL_QPITCH + 2 * FL_STAGEW) * 4)

__global__ void __launch_bounds__(256, 2) flash_tc(
    const __half* __restrict__ gq, const __half* __restrict__ gk,
    const __half* __restrict__ gvt, __half* __restrict__ ctx)
{
  extern __shared__ unsigned smf[];
  unsigned* Qs = smf;
  unsigned* St = smf + 128 * FL_QPITCH;   // 2 stages

  const int bh = blockIdx.y;
  const int b = bh >> 4, h = bh & 15;
  const int tid = threadIdx.x;
  const int warp = tid >> 5, lane = tid & 31;
  const int g = lane >> 2, tk = lane & 3;
  const int l8 = lane & 7, lm = lane >> 3;
  const int m0 = warp * 16;

  const __half* kbase = gk + (size_t)bh * NS * NDH;
  const __half* vtb = gvt + (size_t)bh * NDH * NS;
  const uint32_t sQs = (uint32_t)__cvta_generic_to_shared(Qs);
  const uint32_t sSt = (uint32_t)__cvta_generic_to_shared(St);

  const uint32_t qoff = sQs +
    (uint32_t)(((m0 + l8 + (lm & 1) * 8) * FL_QPITCH + (lm >> 1) * 4) * 4);
  uint32_t koff[4];
  #pragma unroll
  for (int n2 = 0; n2 < 4; n2++)
    koff[n2] = (uint32_t)(((n2 * 16 + l8 + (lm >> 1) * 8) * FL_QPITCH
                           + (lm & 1) * 4) * 4);
  uint32_t voff[8];
  #pragma unroll
  for (int mi = 0; mi < 8; mi++)
    voff[mi] = (uint32_t)((FL_KWORDS + (mi * 16 + l8 + (lm & 1) * 8) * FL_VPITCH
                           + (lm >> 1) * 4) * 4);

  #define FL_ISSUE(t, s) do { \
    if ((t) < ntiles) { \
      const int k0i = (t) * 64; \
      const uint32_t kd = sSt + (uint32_t)(s) * FL_STAGEW * 4; \
      const uint32_t vd = kd + FL_KWORDS * 4; \
      _Pragma("unroll") \
      for (int i = 0; i < 4; i++) { \
        const int id = tid + 256 * i; \
        const int kr = id >> 4, kc = id & 15; \
        cpasync16(kd + (uint32_t)(kr * FL_QPITCH + kc * 4) * 4, \
                  kbase + (size_t)(k0i + kr) * NDH + kc * 8); \
        const int vr = id >> 3, vc = id & 7; \
        cpasync16(vd + (uint32_t)(vr * FL_VPITCH + vc * 4) * 4, \
                  vtb + (size_t)vr * NS + k0i + vc * 8); \
      } \
    } \
    asm volatile("cp.async.commit_group;" ::); \
  } while (0)

  #pragma unroll 1
  for (int pass = 0; pass < 2; pass++) {
    const int qt = (pass == 0) ? (int)blockIdx.x
                               : (NS / 128 - 1 - (int)blockIdx.x);
    const int qb = qt * 128;
    const int qrow_max = qb + m0 + 15;
    const int ntiles = qb / 64 + 2;

    FL_ISSUE(0, 0);
    FL_ISSUE(1, 1);

    // Load Q tile (scale already folded in by the Q-GEMM)
    const __half* qbase = gq + ((size_t)bh * NS + qb) * NDH;
    #pragma unroll
    for (int i = 0; i < 8; i++) {
      int idx = i * 256 + tid;
      int row = idx >> 4, c = idx & 15;
      uint4 v = *(const uint4*)(qbase + (size_t)row * NDH + c * 8);
      *(uint4*)(Qs + row * FL_QPITCH + c * 4) = v;
    }

    float oacc[8][2][4];
    #pragma unroll
    for (int mi = 0; mi < 8; mi++)
      #pragma unroll
      for (int nt = 0; nt < 2; nt++)
        #pragma unroll
        for (int c = 0; c < 4; c++) oacc[mi][nt][c] = 0.f;
    float mrow0 = -1e30f, mrow1 = -1e30f, lrow0 = 0.f, lrow1 = 0.f;

    for (int t = 0; t < ntiles; t++) {
      const int k0 = t * 64;
      const int s = t & 1;
      asm volatile("cp.async.wait_group 1;" ::);
      __syncthreads();

      if (k0 <= qrow_max) {
        const uint32_t stb = sSt + (uint32_t)s * FL_STAGEW * 4;

        float sacc[8][4];
        #pragma unroll
        for (int nt = 0; nt < 8; nt++)
          #pragma unroll
          for (int c = 0; c < 4; c++) sacc[nt][c] = 0.f;

        #pragma unroll
        for (int ks = 0; ks < 8; ks++) {
          unsigned a0, a1, a2, a3;
          ldsm4(a0, a1, a2, a3, qoff + ks * 32);
          unsigned kf[8][2];
          #pragma unroll
          for (int n2 = 0; n2 < 4; n2++)
            ldsm4(kf[2 * n2][0], kf[2 * n2][1], kf[2 * n2 + 1][0],
                  kf[2 * n2 + 1][1], stb + koff[n2] + ks * 32);
          #pragma unroll
          for (int nt = 0; nt < 8; nt++)
            mma_f16(sacc[nt], a0, a1, a2, a3, kf[nt][0], kf[nt][1]);
        }

        if (k0 + 63 > qb + m0) {
          const int r0q = qb + m0 + g, r1q = r0q + 8;
          #pragma unroll
          for (int nt = 0; nt < 8; nt++) {
            const int key0 = k0 + nt * 8 + 2 * tk;
            if (key0     > r0q) sacc[nt][0] = -1e30f;
            if (key0 + 1 > r0q) sacc[nt][1] = -1e30f;
            if (key0     > r1q) sacc[nt][2] = -1e30f;
            if (key0 + 1 > r1q) sacc[nt][3] = -1e30f;
          }
        }

        float mx0 = mrow0, mx1 = mrow1;
        #pragma unroll
        for (int nt = 0; nt < 8; nt++) {
          mx0 = fmaxf(mx0, fmaxf(sacc[nt][0], sacc[nt][1]));
          mx1 = fmaxf(mx1, fmaxf(sacc[nt][2], sacc[nt][3]));
        }
        mx0 = fmaxf(mx0, __shfl_xor_sync(0xffffffffu, mx0, 1));
        mx0 = fmaxf(mx0, __shfl_xor_sync(0xffffffffu, mx0, 2));
        mx1 = fmaxf(mx1, __shfl_xor_sync(0xffffffffu, mx1, 1));
        mx1 = fmaxf(mx1, __shfl_xor_sync(0xffffffffu, mx1, 2));
        const float al0 = __expf(mrow0 - mx0);
        const float al1 = __expf(mrow1 - mx1);
        mrow0 = mx0; mrow1 = mx1;
        lrow0 *= al0; lrow1 *= al1;

        const float af00 = __shfl_sync(0xffffffffu, al0, 8 * tk);
        const float af01 = __shfl_sync(0xffffffffu, al0, 8 * tk + 4);
        const float af10 = __shfl_sync(0xffffffffu, al1, 8 * tk);
        const float af11 = __shfl_sync(0xffffffffu, al1, 8 * tk + 4);
        #pragma unroll
        for (int mi = 0; mi < 8; mi++) {
          oacc[mi][0][0] *= af00; oacc[mi][0][1] *= af01;
          oacc[mi][0][2] *= af00; oacc[mi][0][3] *= af01;
          oacc[mi][1][0] *= af10; oacc[mi][1][1] *= af11;
          oacc[mi][1][2] *= af10; oacc[mi][1][3] *= af11;
        }

        float cb0 = 0.f, cb1 = 0.f;
        #pragma unroll
        for (int nt = 0; nt < 8; nt++) {
          sacc[nt][0] = __expf(sacc[nt][0] - mx0);
          sacc[nt][1] = __expf(sacc[nt][1] - mx0);
          sacc[nt][2] = __expf(sacc[nt][2] - mx1);
          sacc[nt][3] = __expf(sacc[nt][3] - mx1);
          cb0 += sacc[nt][0] + sacc[nt][1];
          cb1 += sacc[nt][2] + sacc[nt][3];
        }
        cb0 += __shfl_xor_sync(0xffffffffu, cb0, 1);
        cb0 += __shfl_xor_sync(0xffffffffu, cb0, 2);
        cb1 += __shfl_xor_sync(0xffffffffu, cb1, 1);
        cb1 += __shfl_xor_sync(0xffffffffu, cb1, 2);
        lrow0 += cb0; lrow1 += cb1;

        #pragma unroll
        for (int ks = 0; ks < 4; ks++) {
          const unsigned bl0 = packh2(sacc[2 * ks][0],     sacc[2 * ks][1]);
          const unsigned bl1 = packh2(sacc[2 * ks + 1][0], sacc[2 * ks + 1][1]);
          const unsigned bh0 = packh2(sacc[2 * ks][2],     sacc[2 * ks][3]);
          const unsigned bh1 = packh2(sacc[2 * ks + 1][2], sacc[2 * ks + 1][3]);
          #pragma unroll
          for (int mi = 0; mi < 8; mi++) {
            unsigned va0, va1, va2, va3;
            ldsm4(va0, va1, va2, va3, stb + voff[mi] + ks * 32);
            mma_f16(oacc[mi][0], va0, va1, va2, va3, bl0, bl1);
            mma_f16(oacc[mi][1], va0, va1, va2, va3, bh0, bh1);
          }
        }
      }

      __syncthreads();          // all warps done reading stage s
      FL_ISSUE(t + 2, s);       // safe to overwrite stage s
    }

    const float l00 = __shfl_sync(0xffffffffu, lrow0, 8 * tk);
    const float l01 = __shfl_sync(0xffffffffu, lrow0, 8 * tk + 4);
    const float l10 = __shfl_sync(0xffffffffu, lrow1, 8 * tk);
    const float l11 = __shfl_sync(0xffffffffu, lrow1, 8 * tk + 4);
    const float i00 = 1.f / l00, i01 = 1.f / l01;
    const float i10 = 1.f / l10, i11 = 1.f / l11;

    __half* cp = ctx + ((size_t)(b * NS + qb + m0)) * ND + h * NDH;
    #pragma unroll
    for (int mi = 0; mi < 8; mi++) {
      const int d0 = mi * 16 + g;
      cp[(size_t)(2 * tk) * ND + d0]         = __float2half_rn(oacc[mi][0][0] * i00);
      cp[(size_t)(2 * tk + 1) * ND + d0]     = __float2half_rn(oacc[mi][0][1] * i01);
      cp[(size_t)(2 * tk) * ND + d0 + 8]     = __float2half_rn(oacc[mi][0][2] * i00);
      cp[(size_t)(2 * tk + 1) * ND + d0 + 8] = __float2half_rn(oacc[mi][0][3] * i01);
      cp[(size_t)(8 + 2 * tk) * ND + d0]     = __float2half_rn(oacc[mi][1][0] * i10);
      cp[(size_t)(9 + 2 * tk) * ND + d0]     = __float2half_rn(oacc[mi][1][1] * i11);
      cp[(size_t)(8 + 2 * tk) * ND + d0 + 8] = __float2half_rn(oacc[mi][1][2] * i10);
      cp[(size_t)(9 + 2 * tk) * ND + d0 + 8] = __float2half_rn(oacc[mi][1][3] * i11);
    }

    __syncthreads();  // pass boundary: Qs/stages reusable
  }
}

extern "C" void kernel_launch(void* const* d_in, const int* in_sizes, int n_in,
                              void* d_out, int out_size) {
  const float* x  = (const float*)d_in[0];
  const float* fc = (const float*)d_in[1];
  const float* fs = (const float*)d_in[2];
  // d_in[3] is the mask; causal handled analytically
  const float* wq = (const float*)d_in[4];
  const float* wk = (const float*)d_in[5];
  const float* wv = (const float*)d_in[6];
  const float* wo = (const float*)d_in[7];

  __half *qh, *kh, *vt, *ctx, *xh, *wqh, *wkh, *wvh, *woh;
  cudaGetSymbolAddress((void**)&qh,  g_qh);
  cudaGetSymbolAddress((void**)&kh,  g_kh);
  cudaGetSymbolAddress((void**)&vt,  g_vt);
  cudaGetSymbolAddress((void**)&ctx, g_ctx);
  cudaGetSymbolAddress((void**)&xh,  g_xh);
  cudaGetSymbolAddress((void**)&wqh, g_wqh);
  cudaGetSymbolAddress((void**)&wkh, g_wkh);
  cudaGetSymbolAddress((void**)&wvh, g_wvh);
  cudaGetSymbolAddress((void**)&woh, g_woh);

  cudaFuncSetAttribute(flash_tc, cudaFuncAttributeMaxDynamicSharedMemorySize, FL_SMEM);
  cudaFuncSetAttribute(gemm_qkv, cudaFuncAttributeMaxDynamicSharedMemorySize, GH_SMEM);
  cudaFuncSetAttribute(gemm_out, cudaFuncAttributeMaxDynamicSharedMemorySize, GH_SMEM);

  // Prep: convert x + all 4 weights to fp16 (2 launches).
  const int nx4 = NM * ND / 4;
  tohalf_k<<<nx4 / 256, 256>>>(x, xh, nx4);
  tohalf4_k<<<4 * (ND * ND / 4) / 256, 256>>>(wq, wk, wv, wo, wqh, wkh, wvh, woh);

  // Fused QKV GEMM: one launch, z = 0/1/2.
  dim3 gq3(ND / 128, NM / 128, 3);
  gemm_qkv<<<gq3, 256, GH_SMEM>>>(xh, wqh, wkh, wvh, qh, kh, vt, fc, fs);

  // Flash: 8 x 32 blocks, causal-balanced pairs (qt, 15-qt).
  dim3 fg(NS / 256, NB * NH);
  flash_tc<<<fg, 256, FL_SMEM>>>(qh, kh, vt, ctx);

  dim3 gg(ND / 128, NM / 128);
  gemm_out<<<gg, 256, GH_SMEM>>>(ctx, woh, (float*)d_out);
}

// round 16
// speedup vs baseline: 1.5436x; 1.1552x over previous
#include <cuda_runtime.h>
#include <cuda_fp16.h>
#include <stdint.h>
#include <math.h>

#define NB 2
#define NS 2048
#define ND 2048
#define NH 16
#define NDH 128
#define NM (NB*NS)

// Scratch (device globals; no allocation allowed)
__device__ __half g_qh[(size_t)NB*NH*NS*NDH];
__device__ __half g_kh[(size_t)NB*NH*NS*NDH];
__device__ __half g_vt[(size_t)NB*NH*NDH*NS];   // V transposed: [b,h,dh,s] fp16
__device__ __half g_ctx[(size_t)NB*NS*ND];      // attention output, fp16
__device__ __half g_xh[(size_t)NM*ND];          // x in fp16
__device__ __half g_wqh[(size_t)ND*ND];
__device__ __half g_wkh[(size_t)ND*ND];
__device__ __half g_wvh[(size_t)ND*ND];
__device__ __half g_woh[(size_t)ND*ND];

__device__ __forceinline__ unsigned packh2(float lo, float hi) {
  __half2 h = __floats2half2_rn(lo, hi);
  return *(unsigned*)&h;
}
__device__ __forceinline__ void mma_f16(float* c, unsigned a0, unsigned a1,
                                        unsigned a2, unsigned a3,
                                        unsigned b0, unsigned b1) {
  asm volatile(
    "mma.sync.aligned.m16n8k16.row.col.f32.f16.f16.f32 "
    "{%0,%1,%2,%3},{%4,%5,%6,%7},{%8,%9},{%0,%1,%2,%3};\n"
    : "+f"(c[0]), "+f"(c[1]), "+f"(c[2]), "+f"(c[3])
    : "r"(a0), "r"(a1), "r"(a2), "r"(a3), "r"(b0), "r"(b1));
}
__device__ __forceinline__ void ldsm4(unsigned& r0, unsigned& r1,
                                      unsigned& r2, unsigned& r3,
                                      uint32_t addr) {
  asm volatile(
    "ldmatrix.sync.aligned.m8n8.x4.shared.b16 {%0,%1,%2,%3}, [%4];"
    : "=r"(r0), "=r"(r1), "=r"(r2), "=r"(r3) : "r"(addr));
}
__device__ __forceinline__ void cpasync16(uint32_t dst, const void* src) {
  asm volatile("cp.async.cg.shared.global [%0], [%1], 16;" :: "r"(dst),
               "l"(src));
}

// fp32 -> fp16 conversion, vectorized.
__global__ void tohalf_k(const float* __restrict__ src,
                         __half* __restrict__ dst, int n4) {
  int i = blockIdx.x * 256 + threadIdx.x;
  if (i < n4) {
    float4 v = ((const float4*)src)[i];
    __half2 h0 = __floats2half2_rn(v.x, v.y);
    __half2 h1 = __floats2half2_rn(v.z, v.w);
    uint2 u = {*(unsigned*)&h0, *(unsigned*)&h1};
    ((uint2*)dst)[i] = u;
  }
}

// 4 weight matrices (ND*ND each) in one launch.
__global__ void tohalf4_k(const float* __restrict__ s0, const float* __restrict__ s1,
                          const float* __restrict__ s2, const float* __restrict__ s3,
                          __half* __restrict__ d0, __half* __restrict__ d1,
                          __half* __restrict__ d2, __half* __restrict__ d3) {
  const int per = (ND * ND / 4) / 256;       // blocks per tensor
  const int which = blockIdx.x / per;
  const int i = (blockIdx.x % per) * 256 + threadIdx.x;
  const float* src = (which == 0) ? s0 : (which == 1) ? s1 : (which == 2) ? s2 : s3;
  __half* dst = (which == 0) ? d0 : (which == 1) ? d1 : (which == 2) ? d2 : d3;
  float4 v = ((const float4*)src)[i];
  __half2 h0 = __floats2half2_rn(v.x, v.y);
  __half2 h1 = __floats2half2_rn(v.z, v.w);
  uint2 u = {*(unsigned*)&h0, *(unsigned*)&h1};
  ((uint2*)dst)[i] = u;
}

// ============================================================================
// GEMM core: fp16 mma.sync + ldmatrix, cp.async 3-stage, 128x128, K-tile 64,
// warp tile 64x32, 2 CTA/SM, one __syncthreads per K-tile.
// Smem rows: 8 x 16B chunks, XOR swizzle chunk^=(row&7): conflict-free
// cp.async stores AND ldmatrix reads. No padding (pitch 32 words).
// ============================================================================
#define GK_STAGEW 4096                 // 128 rows * 32 words
#define GH_SMEM (3 * 2 * GK_STAGEW * 4)

__device__ __forceinline__ void gemm_mainloop(
    const __half* __restrict__ A, const __half* __restrict__ W,
    int bm, int bn, unsigned* smh, float acc[4][4][4])
{
  const int K = ND;
  const int tid = threadIdx.x;
  const int warp = tid >> 5, lane = tid & 31;
  const int wm0 = (warp >> 2) * 64;
  const int wn0 = (warp & 3) * 32;
  const int l8 = lane & 7, lm = lane >> 3;
  const uint32_t sa = (uint32_t)__cvta_generic_to_shared(smh);
  const uint32_t sbm = (uint32_t)__cvta_generic_to_shared(smh + 3 * GK_STAGEW);

  // ldmatrix row params (byte offset of row, row&7, chunk base)
  uint32_t arowb[4], brx_arx[6];  // arx[0..3], brx[4..5]
  uint32_t browb[2];
  #pragma unroll
  for (int mi = 0; mi < 4; mi++) {
    const int row = wm0 + mi * 16 + l8 + (lm & 1) * 8;
    arowb[mi] = (uint32_t)(row * 128);
    brx_arx[mi] = (uint32_t)(row & 7);
  }
  #pragma unroll
  for (int n2 = 0; n2 < 2; n2++) {
    const int row = wn0 + n2 * 16 + l8 + (lm >> 1) * 8;
    browb[n2] = (uint32_t)(row * 128);
    brx_arx[4 + n2] = (uint32_t)(row & 7);
  }
  const uint32_t acb = (uint32_t)(lm >> 1);
  const uint32_t bcb = (uint32_t)(lm & 1);

  // copy mapping: r = id>>3 (row 0..127), c = id&7 (16B chunk), phys = c^(r&7)
  #define GH_ISSUE(kt, st) do { \
    _Pragma("unroll") \
    for (int i = 0; i < 4; i++) { \
      const int id = tid + 256 * i; \
      const int r = id >> 3, c = id & 7; \
      const uint32_t wo = (uint32_t)((st) * GK_STAGEW * 4 + r * 128 \
                                     + ((c ^ (r & 7)) << 4)); \
      cpasync16(sa + wo, A + (size_t)(bm + r) * K + (kt) * 64 + c * 8); \
      cpasync16(sbm + wo, W + (size_t)(bn + r) * K + (kt) * 64 + c * 8); \
    } \
    asm volatile("cp.async.commit_group;" ::); \
  } while (0)

  GH_ISSUE(0, 0);
  GH_ISSUE(1, 1);

  const int niter = K / 64;   // 32
  int st_c = 0, st_p = 2;
  for (int kt = 0; kt < niter; kt++) {
    asm volatile("cp.async.wait_group 1;" ::);
    __syncthreads();
    if (kt + 2 < niter) GH_ISSUE(kt + 2, st_p);
    else asm volatile("cp.async.commit_group;" ::);

    const uint32_t ab = sa + (uint32_t)st_c * GK_STAGEW * 4;
    const uint32_t bb = sbm + (uint32_t)st_c * GK_STAGEW * 4;
    #pragma unroll
    for (int ks = 0; ks < 4; ks++) {
      unsigned afr[4][4], bfr[4][2];
      #pragma unroll
      for (int mi = 0; mi < 4; mi++)
        ldsm4(afr[mi][0], afr[mi][1], afr[mi][2], afr[mi][3],
              ab + arowb[mi] + (((2 * ks + acb) ^ brx_arx[mi]) << 4));
      #pragma unroll
      for (int n2 = 0; n2 < 2; n2++)
        ldsm4(bfr[2 * n2][0], bfr[2 * n2][1], bfr[2 * n2 + 1][0],
              bfr[2 * n2 + 1][1],
              bb + browb[n2] + (((2 * ks + bcb) ^ brx_arx[4 + n2]) << 4));
      #pragma unroll
      for (int mi = 0; mi < 4; mi++)
        #pragma unroll
        for (int ni = 0; ni < 4; ni++)
          mma_f16(acc[mi][ni], afr[mi][0], afr[mi][1], afr[mi][2], afr[mi][3],
                  bfr[ni][0], bfr[ni][1]);
    }
    st_c = (st_c == 2) ? 0 : st_c + 1;
    st_p = (st_p == 2) ? 0 : st_p + 1;
  }
  #undef GH_ISSUE
}

// Fused QKV GEMM: blockIdx.z selects weight + epilogue.
__global__ void __launch_bounds__(256, 2) gemm_qkv(
    const __half* __restrict__ A,
    const __half* __restrict__ Wq, const __half* __restrict__ Wk,
    const __half* __restrict__ Wv,
    __half* __restrict__ Qo, __half* __restrict__ Ko, __half* __restrict__ Vo,
    const float* __restrict__ fcos, const float* __restrict__ fsin)
{
  extern __shared__ unsigned smh[];
  const int z = blockIdx.z;
  const __half* W = (z == 0) ? Wq : (z == 1) ? Wk : Wv;
  const int bm = blockIdx.y * 128;
  const int bn = blockIdx.x * 128;
  const int tid = threadIdx.x;
  const int warp = tid >> 5, lane = tid & 31;
  const int wm0 = (warp >> 2) * 64;
  const int wn0 = (warp & 3) * 32;
  const int g = lane >> 2, tk = lane & 3;

  float acc[4][4][4];
  #pragma unroll
  for (int mi = 0; mi < 4; mi++)
    #pragma unroll
    for (int ni = 0; ni < 4; ni++)
      #pragma unroll
      for (int cc = 0; cc < 4; cc++) acc[mi][ni][cc] = 0.f;

  gemm_mainloop(A, W, bm, bn, smh, acc);

  const float outscale = (z == 0) ? 0.08838834764831845f : 1.0f;
  __half* Ch = (z == 0) ? Qo : (z == 1) ? Ko : Vo;

  #pragma unroll
  for (int mi = 0; mi < 4; mi++) {
    #pragma unroll
    for (int half = 0; half < 2; half++) {
      const int m = bm + wm0 + mi * 16 + g + half * 8;
      const int b = m / NS, s = m % NS;
      #pragma unroll
      for (int ni = 0; ni < 4; ni++) {
        float v0 = acc[mi][ni][half * 2 + 0];
        float v1 = acc[mi][ni][half * 2 + 1];
        const int n = bn + wn0 + ni * 8 + tk * 2;
        const int h = n / NDH, d = n % NDH;
        if (z == 2) {  // V transposed [b,h,dh,s]
          __half* dst = Ch + (((size_t)(b * NH + h)) * NDH + d) * NS + s;
          dst[0]  = __float2half_rn(v0);
          dst[NS] = __float2half_rn(v1);
        } else {       // Q/K: RoPE + head scatter
          __half* dst = Ch + (((size_t)(b * NH + h)) * NS + s) * NDH;
          const int pi = d >> 1;
          const float cc = fcos[s * (NDH / 2) + pi];
          const float sn = fsin[s * (NDH / 2) + pi];
          v0 *= outscale; v1 *= outscale;
          __half2 vv = __floats2half2_rn(v0 * cc - v1 * sn, v0 * sn + v1 * cc);
          *(__half2*)&dst[d] = vv;
        }
      }
    }
  }
}

// Output GEMM (fp32 row-major store), same core.
__global__ void __launch_bounds__(256, 2) gemm_out(
    const __half* __restrict__ A, const __half* __restrict__ W,
    float* __restrict__ C)
{
  extern __shared__ unsigned smh[];
  const int bm = blockIdx.y * 128;
  const int bn = blockIdx.x * 128;
  const int tid = threadIdx.x;
  const int warp = tid >> 5, lane = tid & 31;
  const int wm0 = (warp >> 2) * 64;
  const int wn0 = (warp & 3) * 32;
  const int g = lane >> 2, tk = lane & 3;

  float acc[4][4][4];
  #pragma unroll
  for (int mi = 0; mi < 4; mi++)
    #pragma unroll
    for (int ni = 0; ni < 4; ni++)
      #pragma unroll
      for (int cc = 0; cc < 4; cc++) acc[mi][ni][cc] = 0.f;

  gemm_mainloop(A, W, bm, bn, smh, acc);

  #pragma unroll
  for (int mi = 0; mi < 4; mi++) {
    #pragma unroll
    for (int half = 0; half < 2; half++) {
      const int m = bm + wm0 + mi * 16 + g + half * 8;
      #pragma unroll
      for (int ni = 0; ni < 4; ni++) {
        const int n = bn + wn0 + ni * 8 + tk * 2;
        float2 vv = {acc[mi][ni][half * 2 + 0], acc[mi][ni][half * 2 + 1]};
        *(float2*)&C[(size_t)m * ND + n] = vv;
      }
    }
  }
}

// ============================================================================
// Flash attention (causal), fp16 mma + ldmatrix, 2-stage K/V ring, 2 CTA/SM,
// causal-balanced pairs (qt, 15-qt), XOR-swizzled smem (no pads):
// Q[128][64w], K[64][64w], V[128][32w]; chunk^=(row&7).
// ============================================================================
#define FL_QWORDS (128 * 64)                // 8192 words
#define FL_KWORDS (64 * 64)                 // 4096
#define FL_VWORDS (128 * 32)                // 4096
#define FL_STAGEW (FL_KWORDS + FL_VWORDS)   // 8192
#define FL_SMEM ((FL_QWORDS + 2 * FL_STAGEW) * 4)

__global__ void __launch_bounds__(256, 2) flash_tc(
    const __half* __restrict__ gq, const __half* __restrict__ gk,
    const __half* __restrict__ gvt, __half* __restrict__ ctx)
{
  extern __shared__ unsigned smf[];
  unsigned* Qs = smf;
  unsigned* St = smf + FL_QWORDS;   // 2 stages

  const int bh = blockIdx.y;
  const int b = bh >> 4, h = bh & 15;
  const int tid = threadIdx.x;
  const int warp = tid >> 5, lane = tid & 31;
  const int g = lane >> 2, tk = lane & 3;
  const int l8 = lane & 7, lm = lane >> 3;
  const int m0 = warp * 16;

  const __half* kbase = gk + (size_t)bh * NS * NDH;
  const __half* vtb = gvt + (size_t)bh * NDH * NS;
  const uint32_t sQs = (uint32_t)__cvta_generic_to_shared(Qs);
  const uint32_t sSt = (uint32_t)__cvta_generic_to_shared(St);

  // ldmatrix row params
  const int qrow = m0 + l8 + (lm & 1) * 8;
  const uint32_t qrowb = sQs + (uint32_t)(qrow * 256);
  const uint32_t qrx = (uint32_t)(qrow & 7);
  const uint32_t qcb = (uint32_t)(lm >> 1);
  uint32_t krowb[4], krx[4];
  #pragma unroll
  for (int n2 = 0; n2 < 4; n2++) {
    const int row = n2 * 16 + l8 + (lm >> 1) * 8;
    krowb[n2] = (uint32_t)(row * 256);
    krx[n2] = (uint32_t)(row & 7);
  }
  const uint32_t kcb = (uint32_t)(lm & 1);
  uint32_t vrowb[8], vrx[8];
  #pragma unroll
  for (int mi = 0; mi < 8; mi++) {
    const int row = mi * 16 + l8 + (lm & 1) * 8;
    vrowb[mi] = (uint32_t)(FL_KWORDS * 4 + row * 128);
    vrx[mi] = (uint32_t)(row & 7);
  }
  const uint32_t vcb = (uint32_t)(lm >> 1);

  #define FL_ISSUE(t, s) do { \
    if ((t) < ntiles) { \
      const int k0i = (t) * 64; \
      const uint32_t kd = sSt + (uint32_t)(s) * FL_STAGEW * 4; \
      const uint32_t vd = kd + FL_KWORDS * 4; \
      _Pragma("unroll") \
      for (int i = 0; i < 4; i++) { \
        const int id = tid + 256 * i; \
        const int kr = id >> 4, kc = id & 15; \
        cpasync16(kd + (uint32_t)(kr * 256 + ((kc ^ (kr & 7)) << 4)), \
                  kbase + (size_t)(k0i + kr) * NDH + kc * 8); \
        const int vr = id >> 3, vc = id & 7; \
        cpasync16(vd + (uint32_t)(vr * 128 + ((vc ^ (vr & 7)) << 4)), \
                  vtb + (size_t)vr * NS + k0i + vc * 8); \
      } \
    } \
    asm volatile("cp.async.commit_group;" ::); \
  } while (0)

  #pragma unroll 1
  for (int pass = 0; pass < 2; pass++) {
    const int qt = (pass == 0) ? (int)blockIdx.x
                               : (NS / 128 - 1 - (int)blockIdx.x);
    const int qb = qt * 128;
    const int qrow_max = qb + m0 + 15;
    const int ntiles = qb / 64 + 2;

    FL_ISSUE(0, 0);
    FL_ISSUE(1, 1);

    // Load Q tile (swizzled store; scale already folded in by the Q-GEMM)
    const __half* qbase = gq + ((size_t)bh * NS + qb) * NDH;
    #pragma unroll
    for (int i = 0; i < 8; i++) {
      int idx = i * 256 + tid;
      int row = idx >> 4, c = idx & 15;
      uint4 v = *(const uint4*)(qbase + (size_t)row * NDH + c * 8);
      *(uint4*)(Qs + row * 64 + ((c ^ (row & 7)) * 4)) = v;
    }

    float oacc[8][2][4];
    #pragma unroll
    for (int mi = 0; mi < 8; mi++)
      #pragma unroll
      for (int nt = 0; nt < 2; nt++)
        #pragma unroll
        for (int c = 0; c < 4; c++) oacc[mi][nt][c] = 0.f;
    float mrow0 = -1e30f, mrow1 = -1e30f, lrow0 = 0.f, lrow1 = 0.f;

    for (int t = 0; t < ntiles; t++) {
      const int k0 = t * 64;
      const int s = t & 1;
      asm volatile("cp.async.wait_group 1;" ::);
      __syncthreads();

      if (k0 <= qrow_max) {
        const uint32_t stb = sSt + (uint32_t)s * FL_STAGEW * 4;

        float sacc[8][4];
        #pragma unroll
        for (int nt = 0; nt < 8; nt++)
          #pragma unroll
          for (int c = 0; c < 4; c++) sacc[nt][c] = 0.f;

        #pragma unroll
        for (int ks = 0; ks < 8; ks++) {
          unsigned a0, a1, a2, a3;
          ldsm4(a0, a1, a2, a3, qrowb + (((2 * ks + qcb) ^ qrx) << 4));
          unsigned kf[8][2];
          #pragma unroll
          for (int n2 = 0; n2 < 4; n2++)
            ldsm4(kf[2 * n2][0], kf[2 * n2][1], kf[2 * n2 + 1][0],
                  kf[2 * n2 + 1][1],
                  stb + krowb[n2] + (((2 * ks + kcb) ^ krx[n2]) << 4));
          #pragma unroll
          for (int nt = 0; nt < 8; nt++)
            mma_f16(sacc[nt], a0, a1, a2, a3, kf[nt][0], kf[nt][1]);
        }

        if (k0 + 63 > qb + m0) {
          const int r0q = qb + m0 + g, r1q = r0q + 8;
          #pragma unroll
          for (int nt = 0; nt < 8; nt++) {
            const int key0 = k0 + nt * 8 + 2 * tk;
            if (key0     > r0q) sacc[nt][0] = -1e30f;
            if (key0 + 1 > r0q) sacc[nt][1] = -1e30f;
            if (key0     > r1q) sacc[nt][2] = -1e30f;
            if (key0 + 1 > r1q) sacc[nt][3] = -1e30f;
          }
        }

        float mx0 = mrow0, mx1 = mrow1;
        #pragma unroll
        for (int nt = 0; nt < 8; nt++) {
          mx0 = fmaxf(mx0, fmaxf(sacc[nt][0], sacc[nt][1]));
          mx1 = fmaxf(mx1, fmaxf(sacc[nt][2], sacc[nt][3]));
        }
        mx0 = fmaxf(mx0, __shfl_xor_sync(0xffffffffu, mx0, 1));
        mx0 = fmaxf(mx0, __shfl_xor_sync(0xffffffffu, mx0, 2));
        mx1 = fmaxf(mx1, __shfl_xor_sync(0xffffffffu, mx1, 1));
        mx1 = fmaxf(mx1, __shfl_xor_sync(0xffffffffu, mx1, 2));
        const float al0 = __expf(mrow0 - mx0);
        const float al1 = __expf(mrow1 - mx1);
        mrow0 = mx0; mrow1 = mx1;
        lrow0 *= al0; lrow1 *= al1;

        const float af00 = __shfl_sync(0xffffffffu, al0, 8 * tk);
        const float af01 = __shfl_sync(0xffffffffu, al0, 8 * tk + 4);
        const float af10 = __shfl_sync(0xffffffffu, al1, 8 * tk);
        const float af11 = __shfl_sync(0xffffffffu, al1, 8 * tk + 4);
        #pragma unroll
        for (int mi = 0; mi < 8; mi++) {
          oacc[mi][0][0] *= af00; oacc[mi][0][1] *= af01;
          oacc[mi][0][2] *= af00; oacc[mi][0][3] *= af01;
          oacc[mi][1][0] *= af10; oacc[mi][1][1] *= af11;
          oacc[mi][1][2] *= af10; oacc[mi][1][3] *= af11;
        }

        float cb0 = 0.f, cb1 = 0.f;
        #pragma unroll
        for (int nt = 0; nt < 8; nt++) {
          sacc[nt][0] = __expf(sacc[nt][0] - mx0);
          sacc[nt][1] = __expf(sacc[nt][1] - mx0);
          sacc[nt][2] = __expf(sacc[nt][2] - mx1);
          sacc[nt][3] = __expf(sacc[nt][3] - mx1);
          cb0 += sacc[nt][0] + sacc[nt][1];
          cb1 += sacc[nt][2] + sacc[nt][3];
        }
        cb0 += __shfl_xor_sync(0xffffffffu, cb0, 1);
        cb0 += __shfl_xor_sync(0xffffffffu, cb0, 2);
        cb1 += __shfl_xor_sync(0xffffffffu, cb1, 1);
        cb1 += __shfl_xor_sync(0xffffffffu, cb1, 2);
        lrow0 += cb0; lrow1 += cb1;

        #pragma unroll
        for (int ks = 0; ks < 4; ks++) {
          const unsigned bl0 = packh2(sacc[2 * ks][0],     sacc[2 * ks][1]);
          const unsigned bl1 = packh2(sacc[2 * ks + 1][0], sacc[2 * ks + 1][1]);
          const unsigned bh0 = packh2(sacc[2 * ks][2],     sacc[2 * ks][3]);
          const unsigned bh1 = packh2(sacc[2 * ks + 1][2], sacc[2 * ks + 1][3]);
          #pragma unroll
          for (int mi = 0; mi < 8; mi++) {
            unsigned va0, va1, va2, va3;
            ldsm4(va0, va1, va2, va3,
                  stb + vrowb[mi] + (((2 * ks + vcb) ^ vrx[mi]) << 4));
            mma_f16(oacc[mi][0], va0, va1, va2, va3, bl0, bl1);
            mma_f16(oacc[mi][1], va0, va1, va2, va3, bh0, bh1);
          }
        }
      }

      __syncthreads();          // all warps done reading stage s
      FL_ISSUE(t + 2, s);       // safe to overwrite stage s
    }

    const float l00 = __shfl_sync(0xffffffffu, lrow0, 8 * tk);
    const float l01 = __shfl_sync(0xffffffffu, lrow0, 8 * tk + 4);
    const float l10 = __shfl_sync(0xffffffffu, lrow1, 8 * tk);
    const float l11 = __shfl_sync(0xffffffffu, lrow1, 8 * tk + 4);
    const float i00 = 1.f / l00, i01 = 1.f / l01;
    const float i10 = 1.f / l10, i11 = 1.f / l11;

    __half* cp = ctx + ((size_t)(b * NS + qb + m0)) * ND + h * NDH;
    #pragma unroll
    for (int mi = 0; mi < 8; mi++) {
      const int d0 = mi * 16 + g;
      cp[(size_t)(2 * tk) * ND + d0]         = __float2half_rn(oacc[mi][0][0] * i00);
      cp[(size_t)(2 * tk + 1) * ND + d0]     = __float2half_rn(oacc[mi][0][1] * i01);
      cp[(size_t)(2 * tk) * ND + d0 + 8]     = __float2half_rn(oacc[mi][0][2] * i00);
      cp[(size_t)(2 * tk + 1) * ND + d0 + 8] = __float2half_rn(oacc[mi][0][3] * i01);
      cp[(size_t)(8 + 2 * tk) * ND + d0]     = __float2half_rn(oacc[mi][1][0] * i10);
      cp[(size_t)(9 + 2 * tk) * ND + d0]     = __float2half_rn(oacc[mi][1][1] * i11);
      cp[(size_t)(8 + 2 * tk) * ND + d0 + 8] = __float2half_rn(oacc[mi][1][2] * i10);
      cp[(size_t)(9 + 2 * tk) * ND + d0 + 8] = __float2half_rn(oacc[mi][1][3] * i11);
    }

    __syncthreads();  // pass boundary: Qs/stages reusable
  }
}

extern "C" void kernel_launch(void* const* d_in, const int* in_sizes, int n_in,
                              void* d_out, int out_size) {
  const float* x  = (const float*)d_in[0];
  const float* fc = (const float*)d_in[1];
  const float* fs = (const float*)d_in[2];
  // d_in[3] is the mask; causal handled analytically
  const float* wq = (const float*)d_in[4];
  const float* wk = (const float*)d_in[5];
  const float* wv = (const float*)d_in[6];
  const float* wo = (const float*)d_in[7];

  __half *qh, *kh, *vt, *ctx, *xh, *wqh, *wkh, *wvh, *woh;
  cudaGetSymbolAddress((void**)&qh,  g_qh);
  cudaGetSymbolAddress((void**)&kh,  g_kh);
  cudaGetSymbolAddress((void**)&vt,  g_vt);
  cudaGetSymbolAddress((void**)&ctx, g_ctx);
  cudaGetSymbolAddress((void**)&xh,  g_xh);
  cudaGetSymbolAddress((void**)&wqh, g_wqh);
  cudaGetSymbolAddress((void**)&wkh, g_wkh);
  cudaGetSymbolAddress((void**)&wvh, g_wvh);
  cudaGetSymbolAddress((void**)&woh, g_woh);

  cudaFuncSetAttribute(flash_tc, cudaFuncAttributeMaxDynamicSharedMemorySize, FL_SMEM);
  cudaFuncSetAttribute(gemm_qkv, cudaFuncAttributeMaxDynamicSharedMemorySize, GH_SMEM);
  cudaFuncSetAttribute(gemm_out, cudaFuncAttributeMaxDynamicSharedMemorySize, GH_SMEM);

  // Prep: convert x + all 4 weights to fp16 (2 launches).
  const int nx4 = NM * ND / 4;
  tohalf_k<<<nx4 / 256, 256>>>(x, xh, nx4);
  tohalf4_k<<<4 * (ND * ND / 4) / 256, 256>>>(wq, wk, wv, wo, wqh, wkh, wvh, woh);

  // Fused QKV GEMM: one launch, z = 0/1/2.
  dim3 gq3(ND / 128, NM / 128, 3);
  gemm_qkv<<<gq3, 256, GH_SMEM>>>(xh, wqh, wkh, wvh, qh, kh, vt, fc, fs);

  // Flash: 8 x 32 blocks, causal-balanced pairs (qt, 15-qt).
  dim3 fg(NS / 256, NB * NH);
  flash_tc<<<fg, 256, FL_SMEM>>>(qh, kh, vt, ctx);

  dim3 gg(ND / 128, NM / 128);
  gemm_out<<<gg, 256, GH_SMEM>>>(ctx, woh, (float*)d_out);
}